// round 3
// baseline (speedup 1.0000x reference)
#include <cuda_runtime.h>
#include <cuda_bf16.h>
#include <math.h>

#define SEQ   2048
#define NH    16
#define NKV   4
#define DQK   192
#define DNOPE 128
#define DROPE 64
#define DV    128
#define DM    2048
#define QRANK 1536
#define KVRANK 512

// ---------------- scratch (static device globals; allocation-free) ----------------
__device__ float g_qa  [SEQ * QRANK];
__device__ float g_qan [SEQ * QRANK];
__device__ float g_q   [SEQ * NH * DQK];
__device__ float g_ckv [SEQ * (KVRANK + DROPE)];
__device__ float g_ckvn[SEQ * KVRANK];
__device__ float g_kv  [SEQ * NKV * (DNOPE + DV)];
__device__ float g_qf  [NH  * SEQ * DQK];
__device__ float g_k   [NKV * SEQ * DQK];
__device__ float g_v   [NKV * SEQ * DV];
__device__ float g_sc  [67108864];                    // NH*SEQ*SEQ
__device__ float g_ao  [SEQ * NH * DV];

// ---------------- generic tiled SGEMM: C[M,N] = A[M,K] @ B[K,N] ----------------
#define BM 64
#define BN 64
#define BK 16
#define TM 4
#define TN 4

// kcap != 0 : only accumulate k < row0 + BM  (causal cap for P@V)
__global__ __launch_bounds__(256)
void sgemm_nn(const float* __restrict__ A, const float* __restrict__ B,
              float* __restrict__ C, int M, int N, int K,
              int lda, int ldb, int ldc, int kcap) {
    __shared__ float As[BK][BM + 1];
    __shared__ float Bs[BK][BN + 1];
    const int tid  = threadIdx.x;
    const int row0 = blockIdx.y * BM;
    const int col0 = blockIdx.x * BN;
    const int tr = (tid / (BN / TN)) * TM;
    const int tc = (tid % (BN / TN)) * TN;

    int Keff = K;
    if (kcap) { int lim = row0 + BM; if (lim < Keff) Keff = lim; }

    float acc[TM][TN];
#pragma unroll
    for (int i = 0; i < TM; i++)
#pragma unroll
        for (int j = 0; j < TN; j++) acc[i][j] = 0.f;

    for (int k0 = 0; k0 < Keff; k0 += BK) {
        for (int i = tid; i < BM * BK; i += 256) {
            int m = i / BK, kk = i % BK;
            As[kk][m] = A[(size_t)(row0 + m) * lda + k0 + kk];
        }
        for (int i = tid; i < BK * BN; i += 256) {
            int kk = i / BN, n = i % BN;
            Bs[kk][n] = B[(size_t)(k0 + kk) * ldb + col0 + n];
        }
        __syncthreads();
#pragma unroll
        for (int kk = 0; kk < BK; kk++) {
            float a[TM], b[TN];
#pragma unroll
            for (int i = 0; i < TM; i++) a[i] = As[kk][tr + i];
#pragma unroll
            for (int j = 0; j < TN; j++) b[j] = Bs[kk][tc + j];
#pragma unroll
            for (int i = 0; i < TM; i++)
#pragma unroll
                for (int j = 0; j < TN; j++) acc[i][j] += a[i] * b[j];
        }
        __syncthreads();
    }
#pragma unroll
    for (int i = 0; i < TM; i++)
#pragma unroll
        for (int j = 0; j < TN; j++)
            C[(size_t)(row0 + tr + i) * ldc + col0 + tc + j] = acc[i][j];
}

// ---------------- scores: S[h][q][k] = scale * Qf[h,q,:] . K[h/4,k,:] ----------------
__global__ __launch_bounds__(256)
void scores_nt(const float* __restrict__ Qf, const float* __restrict__ Kk,
               float* __restrict__ Sc, float scale) {
    const int h  = blockIdx.z;
    const int q0 = blockIdx.y * BM;
    const int k0 = blockIdx.x * BN;
    if (k0 > q0 + BM - 1) return;   // fully above diagonal: never read

    const float* A = Qf + (size_t)h * SEQ * DQK;
    const float* B = Kk + (size_t)(h / 4) * SEQ * DQK;
    float*       C = Sc + (size_t)h * SEQ * SEQ;

    __shared__ float As[BK][BM + 1];
    __shared__ float Bs[BK][BN + 1];
    const int tid = threadIdx.x;
    const int tr = (tid / (BN / TN)) * TM;
    const int tc = (tid % (BN / TN)) * TN;

    float acc[TM][TN];
#pragma unroll
    for (int i = 0; i < TM; i++)
#pragma unroll
        for (int j = 0; j < TN; j++) acc[i][j] = 0.f;

    for (int c0 = 0; c0 < DQK; c0 += BK) {
        for (int i = tid; i < BM * BK; i += 256) {
            int m = i / BK, kk = i % BK;
            As[kk][m] = A[(size_t)(q0 + m) * DQK + c0 + kk];
        }
        for (int i = tid; i < BN * BK; i += 256) {
            int kk = i % BK, n = i / BK;
            Bs[kk][n] = B[(size_t)(k0 + n) * DQK + c0 + kk];
        }
        __syncthreads();
#pragma unroll
        for (int kk = 0; kk < BK; kk++) {
            float a[TM], b[TN];
#pragma unroll
            for (int i = 0; i < TM; i++) a[i] = As[kk][tr + i];
#pragma unroll
            for (int j = 0; j < TN; j++) b[j] = Bs[kk][tc + j];
#pragma unroll
            for (int i = 0; i < TM; i++)
#pragma unroll
                for (int j = 0; j < TN; j++) acc[i][j] += a[i] * b[j];
        }
        __syncthreads();
    }
#pragma unroll
    for (int i = 0; i < TM; i++)
#pragma unroll
        for (int j = 0; j < TN; j++)
            C[(size_t)(q0 + tr + i) * SEQ + k0 + tc + j] = acc[i][j] * scale;
}

// ---------------- row softmax over k<=q, zeros beyond (in-place) ----------------
__global__ __launch_bounds__(256)
void softmax_causal(float* __restrict__ Sc) {
    const int r = blockIdx.x;             // r = h*SEQ + q
    const int q = r & (SEQ - 1);
    float* row = Sc + (size_t)r * SEQ;
    const int n = q + 1;
    const int tid = threadIdx.x;
    __shared__ float red[256];

    float m = -INFINITY;
    for (int j = tid; j < n; j += 256) m = fmaxf(m, row[j]);
    red[tid] = m; __syncthreads();
    for (int s = 128; s > 0; s >>= 1) {
        if (tid < s) red[tid] = fmaxf(red[tid], red[tid + s]);
        __syncthreads();
    }
    m = red[0]; __syncthreads();

    float sum = 0.f;
    for (int j = tid; j < n; j += 256) {
        float e = expf(row[j] - m);
        row[j] = e;
        sum += e;
    }
    red[tid] = sum; __syncthreads();
    for (int s = 128; s > 0; s >>= 1) {
        if (tid < s) red[tid] += red[tid + s];
        __syncthreads();
    }
    const float inv = 1.f / red[0];
    for (int j = tid; j < n; j += 256) row[j] *= inv;
    for (int j = n + tid; j < SEQ; j += 256) row[j] = 0.f;
}

// ---------------- rms norm: one block per row ----------------
__global__ __launch_bounds__(256)
void rmsnorm(const float* __restrict__ X, float* __restrict__ Y,
             const float* __restrict__ W, int n, int ldx, int ldy) {
    const int r = blockIdx.x;
    const float* x = X + (size_t)r * ldx;
    float*       y = Y + (size_t)r * ldy;
    const int tid = threadIdx.x;
    __shared__ float red[256];

    float ss = 0.f;
    for (int j = tid; j < n; j += 256) { float v = x[j]; ss += v * v; }
    red[tid] = ss; __syncthreads();
    for (int s = 128; s > 0; s >>= 1) {
        if (tid < s) red[tid] += red[tid + s];
        __syncthreads();
    }
    const float rinv = rsqrtf(red[0] / (float)n + 1e-6f);
    for (int j = tid; j < n; j += 256) y[j] = x[j] * rinv * W[j];
}

// ---------------- RoPE + head gather: one block per sequence position ----------------
__global__ __launch_bounds__(256)
void rope_gather(const float* __restrict__ q,   // [SEQ, NH*DQK]
                 const float* __restrict__ kv,  // [SEQ, NKV*(DNOPE+DV)]
                 const float* __restrict__ ckv, // [SEQ, KVRANK+DROPE]
                 const float* __restrict__ cosT, const float* __restrict__ sinT,
                 const int* __restrict__ pos,   // int32! (JAX silently downgrades int64)
                 float* __restrict__ qf,        // [NH, SEQ, DQK]
                 float* __restrict__ kk,        // [NKV, SEQ, DQK]
                 float* __restrict__ vv) {      // [NKV, SEQ, DV]
    const int s = blockIdx.x;
    const int p = pos[s];
    const float* c  = cosT + (size_t)p * DROPE;
    const float* sn = sinT + (size_t)p * DROPE;

    // Q heads
    for (int i = threadIdx.x; i < NH * DQK; i += 256) {
        int h = i / DQK, d = i % DQK;
        const float* qr = q + (size_t)s * NH * DQK + h * DQK;
        float val;
        if (d < DNOPE) val = qr[d];
        else {
            int dr = d - DNOPE;
            float x  = qr[d];
            float rh = (dr < DROPE / 2) ? -qr[DNOPE + dr + DROPE / 2]
                                        :  qr[DNOPE + dr - DROPE / 2];
            val = x * c[dr] + rh * sn[dr];
        }
        qf[((size_t)h * SEQ + s) * DQK + d] = val;
    }
    // K heads (nope from kv_b output; rope part shared, from ckv tail)
    for (int i = threadIdx.x; i < NKV * DQK; i += 256) {
        int kh = i / DQK, d = i % DQK;
        float val;
        if (d < DNOPE) val = kv[(size_t)s * NKV * (DNOPE + DV) + kh * (DNOPE + DV) + d];
        else {
            int dr = d - DNOPE;
            const float* kr = ckv + (size_t)s * (KVRANK + DROPE) + KVRANK;
            float x  = kr[dr];
            float rh = (dr < DROPE / 2) ? -kr[dr + DROPE / 2] : kr[dr - DROPE / 2];
            val = x * c[dr] + rh * sn[dr];
        }
        kk[((size_t)kh * SEQ + s) * DQK + d] = val;
    }
    // V heads
    for (int i = threadIdx.x; i < NKV * DV; i += 256) {
        int kh = i / DV, d = i % DV;
        vv[((size_t)kh * SEQ + s) * DV + d] =
            kv[(size_t)s * NKV * (DNOPE + DV) + kh * (DNOPE + DV) + DNOPE + d];
    }
}

// ---------------- launch ----------------
extern "C" void kernel_launch(void* const* d_in, const int* in_sizes, int n_in,
                              void* d_out, int out_size) {
    const float* hidden    = (const float*)d_in[0];
    const float* cosT      = (const float*)d_in[1];
    const float* sinT      = (const float*)d_in[2];
    const float* wq_a      = (const float*)d_in[3];
    const float* q_a_ln_w  = (const float*)d_in[4];
    const float* wq_b      = (const float*)d_in[5];
    const float* wkv_a     = (const float*)d_in[6];
    const float* kv_a_ln_w = (const float*)d_in[7];
    const float* wkv_b     = (const float*)d_in[8];
    const float* wo        = (const float*)d_in[9];
    const int*   cpos      = (const int*)d_in[10];   // int32 (JAX x64 disabled)
    float* out = (float*)d_out;

    float *qa, *qan, *q, *ckv, *ckvn, *kv, *qf, *k, *v, *sc, *ao;
    cudaGetSymbolAddress((void**)&qa,   g_qa);
    cudaGetSymbolAddress((void**)&qan,  g_qan);
    cudaGetSymbolAddress((void**)&q,    g_q);
    cudaGetSymbolAddress((void**)&ckv,  g_ckv);
    cudaGetSymbolAddress((void**)&ckvn, g_ckvn);
    cudaGetSymbolAddress((void**)&kv,   g_kv);
    cudaGetSymbolAddress((void**)&qf,   g_qf);
    cudaGetSymbolAddress((void**)&k,    g_k);
    cudaGetSymbolAddress((void**)&v,    g_v);
    cudaGetSymbolAddress((void**)&sc,   g_sc);
    cudaGetSymbolAddress((void**)&ao,   g_ao);

    // 1) q_a = hidden @ wq_a          [2048,2048]x[2048,1536]
    sgemm_nn<<<dim3(QRANK / BN, SEQ / BM), 256>>>(hidden, wq_a, qa,
        SEQ, QRANK, DM, DM, QRANK, QRANK, 0);
    // 2) rmsnorm q_a
    rmsnorm<<<SEQ, 256>>>(qa, qan, q_a_ln_w, QRANK, QRANK, QRANK);
    // 3) q = qan @ wq_b               [2048,1536]x[1536,3072]
    sgemm_nn<<<dim3(NH * DQK / BN, SEQ / BM), 256>>>(qan, wq_b, q,
        SEQ, NH * DQK, QRANK, QRANK, NH * DQK, NH * DQK, 0);
    // 4) ckv = hidden @ wkv_a         [2048,2048]x[2048,576]
    sgemm_nn<<<dim3((KVRANK + DROPE) / BN, SEQ / BM), 256>>>(hidden, wkv_a, ckv,
        SEQ, KVRANK + DROPE, DM, DM, KVRANK + DROPE, KVRANK + DROPE, 0);
    // 5) rmsnorm ckv[:, :512]
    rmsnorm<<<SEQ, 256>>>(ckv, ckvn, kv_a_ln_w, KVRANK, KVRANK + DROPE, KVRANK);
    // 6) kv = ckvn @ wkv_b            [2048,512]x[512,1024]
    sgemm_nn<<<dim3(NKV * (DNOPE + DV) / BN, SEQ / BM), 256>>>(ckvn, wkv_b, kv,
        SEQ, NKV * (DNOPE + DV), KVRANK, KVRANK, NKV * (DNOPE + DV), NKV * (DNOPE + DV), 0);
    // 7) RoPE + gather
    rope_gather<<<SEQ, 256>>>(q, kv, ckv, cosT, sinT, cpos, qf, k, v);
    // 8) scores (causal-skipped)
    scores_nt<<<dim3(SEQ / BN, SEQ / BM, NH), 256>>>(qf, k, sc, rsqrtf((float)DQK));
    // 9) causal softmax in place
    softmax_causal<<<NH * SEQ, 256>>>(sc);
    // 10) per-head P @ V, causal-capped K
    for (int h = 0; h < NH; h++) {
        sgemm_nn<<<dim3(DV / BN, SEQ / BM), 256>>>(
            sc + (size_t)h * SEQ * SEQ, v + (size_t)(h / 4) * SEQ * DV, ao + (size_t)h * DV,
            SEQ, DV, SEQ, SEQ, DV, NH * DV, 1);
    }
    // 11) out = ao @ wo               [2048,2048]x[2048,2048]
    sgemm_nn<<<dim3(DM / BN, SEQ / BM), 256>>>(ao, wo, out,
        SEQ, DM, NH * DV, NH * DV, DM, DM, 0);
}

// round 6
// speedup vs baseline: 3.6759x; 3.6759x over previous
#include <cuda_runtime.h>
#include <cuda_bf16.h>
#include <math.h>

#define SEQ   2048
#define NH    16
#define NKV   4
#define DQK   192
#define DNOPE 128
#define DROPE 64
#define DV    128
#define DM    2048
#define QRANK 1536
#define KVRANK 512

// ---------------- scratch (static device globals; allocation-free) ----------------
__device__ float g_qa  [SEQ * QRANK];
__device__ float g_qan [SEQ * QRANK];
__device__ float g_q   [SEQ * NH * DQK];
__device__ float g_ckv [SEQ * (KVRANK + DROPE)];
__device__ float g_ckvn[SEQ * KVRANK];
__device__ float g_kv  [SEQ * NKV * (DNOPE + DV)];
__device__ float g_qf  [NH  * SEQ * DQK];
__device__ float g_k   [NKV * SEQ * DQK];
__device__ float g_v   [NKV * SEQ * DV];
__device__ float g_sc  [67108864];                    // NH*SEQ*SEQ
__device__ float g_ao  [SEQ * NH * DV];

// ================= 128x128x8 double-buffered SGEMM, 8x8 per thread =============
#define BM 128
#define BN 128
#define BK 8

// KCAP: Keff = min(K, row0+BM) (causal P@V).  NG: guard N (for N=576).
// Batch: A += z*zA, B += (z>>zshiftB)*zB, C += z*zC.
template<int KCAP, bool NG>
__global__ __launch_bounds__(256)
void sgemm128(const float* __restrict__ A, const float* __restrict__ B,
              float* __restrict__ C, int M, int N, int K,
              int lda, int ldb, int ldc,
              size_t zA, size_t zB, size_t zC, int zshiftB) {
    __shared__ float As[2][BK][BM + 4];
    __shared__ float Bs[2][BK][BN];

    const int z = blockIdx.z;
    A += (size_t)z * zA;
    B += (size_t)(z >> zshiftB) * zB;
    C += (size_t)z * zC;

    const int tid  = threadIdx.x;
    const int row0 = blockIdx.y * BM;
    const int col0 = blockIdx.x * BN;

    int Keff = K;
    if (KCAP) { int lim = row0 + BM; if (lim < Keff) Keff = lim; }

    // loader mapping
    const int am = tid >> 1;            // 0..127
    const int ak = (tid & 1) * 4;       // 0 or 4
    const int bk = tid >> 5;            // 0..7
    const int bn = (tid & 31) * 4;      // 0..124
    // compute mapping
    const int tr = (tid >> 4) * 8;
    const int tc = (tid & 15) * 8;

    float acc[8][8];
#pragma unroll
    for (int i = 0; i < 8; i++)
#pragma unroll
        for (int j = 0; j < 8; j++) acc[i][j] = 0.f;

    float4 ra, rb;
    // prologue: load k0=0
    ra = *(const float4*)&A[(size_t)(row0 + am) * lda + ak];
    if (!NG || col0 + bn + 3 < N)
        rb = *(const float4*)&B[(size_t)bk * ldb + col0 + bn];
    else rb = make_float4(0.f, 0.f, 0.f, 0.f);

    int s = 0;
    As[0][ak + 0][am] = ra.x; As[0][ak + 1][am] = ra.y;
    As[0][ak + 2][am] = ra.z; As[0][ak + 3][am] = ra.w;
    *(float4*)&Bs[0][bk][bn] = rb;
    __syncthreads();

    for (int k0 = BK; k0 < Keff; k0 += BK) {
        // prefetch next tile into regs
        ra = *(const float4*)&A[(size_t)(row0 + am) * lda + k0 + ak];
        if (!NG || col0 + bn + 3 < N)
            rb = *(const float4*)&B[(size_t)(k0 + bk) * ldb + col0 + bn];
        else rb = make_float4(0.f, 0.f, 0.f, 0.f);

        // compute current buffer
#pragma unroll
        for (int kk = 0; kk < BK; kk++) {
            float4 a0 = *(float4*)&As[s][kk][tr];
            float4 a1 = *(float4*)&As[s][kk][tr + 4];
            float4 b0 = *(float4*)&Bs[s][kk][tc];
            float4 b1 = *(float4*)&Bs[s][kk][tc + 4];
            float a[8] = {a0.x,a0.y,a0.z,a0.w,a1.x,a1.y,a1.z,a1.w};
            float b[8] = {b0.x,b0.y,b0.z,b0.w,b1.x,b1.y,b1.z,b1.w};
#pragma unroll
            for (int i = 0; i < 8; i++)
#pragma unroll
                for (int j = 0; j < 8; j++) acc[i][j] += a[i] * b[j];
        }

        // stage into other buffer
        As[s ^ 1][ak + 0][am] = ra.x; As[s ^ 1][ak + 1][am] = ra.y;
        As[s ^ 1][ak + 2][am] = ra.z; As[s ^ 1][ak + 3][am] = ra.w;
        *(float4*)&Bs[s ^ 1][bk][bn] = rb;
        __syncthreads();
        s ^= 1;
    }
    // final tile
#pragma unroll
    for (int kk = 0; kk < BK; kk++) {
        float4 a0 = *(float4*)&As[s][kk][tr];
        float4 a1 = *(float4*)&As[s][kk][tr + 4];
        float4 b0 = *(float4*)&Bs[s][kk][tc];
        float4 b1 = *(float4*)&Bs[s][kk][tc + 4];
        float a[8] = {a0.x,a0.y,a0.z,a0.w,a1.x,a1.y,a1.z,a1.w};
        float b[8] = {b0.x,b0.y,b0.z,b0.w,b1.x,b1.y,b1.z,b1.w};
#pragma unroll
        for (int i = 0; i < 8; i++)
#pragma unroll
            for (int j = 0; j < 8; j++) acc[i][j] += a[i] * b[j];
    }

    // epilogue
#pragma unroll
    for (int i = 0; i < 8; i++) {
        float* cr = &C[(size_t)(row0 + tr + i) * ldc + col0 + tc];
        if (!NG || col0 + tc + 3 < N)
            *(float4*)cr = make_float4(acc[i][0], acc[i][1], acc[i][2], acc[i][3]);
        if (!NG || col0 + tc + 7 < N)
            *(float4*)(cr + 4) = make_float4(acc[i][4], acc[i][5], acc[i][6], acc[i][7]);
    }
}

// ============ scores (NT, batched over heads, causal-skipped) ===================
// S[h][q][k] = scale * Qf[h,q,:] . K[h/4,k,:]
__global__ __launch_bounds__(256)
void scores128(const float* __restrict__ Qf, const float* __restrict__ Kk,
               float* __restrict__ Sc, float scale) {
    const int h  = blockIdx.z;
    const int q0 = blockIdx.y * BM;
    const int k0b = blockIdx.x * BN;
    if (k0b > q0 + BM - 1) return;   // fully above diagonal: never consumed

    const float* A = Qf + (size_t)h * SEQ * DQK;
    const float* B = Kk + (size_t)(h >> 2) * SEQ * DQK;
    float*       C = Sc + (size_t)h * SEQ * SEQ;

    __shared__ float As[2][BK][BM + 4];
    __shared__ float Bs[2][BK][BN + 4];

    const int tid = threadIdx.x;
    const int am = tid >> 1, ak = (tid & 1) * 4;
    const int bm = tid >> 1, bd = (tid & 1) * 4;   // B row (k index), d offset
    const int tr = (tid >> 4) * 8, tc = (tid & 15) * 8;

    float acc[8][8];
#pragma unroll
    for (int i = 0; i < 8; i++)
#pragma unroll
        for (int j = 0; j < 8; j++) acc[i][j] = 0.f;

    float4 ra, rb;
    ra = *(const float4*)&A[(size_t)(q0 + am) * DQK + ak];
    rb = *(const float4*)&B[(size_t)(k0b + bm) * DQK + bd];

    int s = 0;
    As[0][ak + 0][am] = ra.x; As[0][ak + 1][am] = ra.y;
    As[0][ak + 2][am] = ra.z; As[0][ak + 3][am] = ra.w;
    Bs[0][bd + 0][bm] = rb.x; Bs[0][bd + 1][bm] = rb.y;
    Bs[0][bd + 2][bm] = rb.z; Bs[0][bd + 3][bm] = rb.w;
    __syncthreads();

    for (int c0 = BK; c0 < DQK; c0 += BK) {
        ra = *(const float4*)&A[(size_t)(q0 + am) * DQK + c0 + ak];
        rb = *(const float4*)&B[(size_t)(k0b + bm) * DQK + c0 + bd];

#pragma unroll
        for (int kk = 0; kk < BK; kk++) {
            float4 a0 = *(float4*)&As[s][kk][tr];
            float4 a1 = *(float4*)&As[s][kk][tr + 4];
            float4 b0 = *(float4*)&Bs[s][kk][tc];
            float4 b1 = *(float4*)&Bs[s][kk][tc + 4];
            float a[8] = {a0.x,a0.y,a0.z,a0.w,a1.x,a1.y,a1.z,a1.w};
            float b[8] = {b0.x,b0.y,b0.z,b0.w,b1.x,b1.y,b1.z,b1.w};
#pragma unroll
            for (int i = 0; i < 8; i++)
#pragma unroll
                for (int j = 0; j < 8; j++) acc[i][j] += a[i] * b[j];
        }

        As[s ^ 1][ak + 0][am] = ra.x; As[s ^ 1][ak + 1][am] = ra.y;
        As[s ^ 1][ak + 2][am] = ra.z; As[s ^ 1][ak + 3][am] = ra.w;
        Bs[s ^ 1][bd + 0][bm] = rb.x; Bs[s ^ 1][bd + 1][bm] = rb.y;
        Bs[s ^ 1][bd + 2][bm] = rb.z; Bs[s ^ 1][bd + 3][bm] = rb.w;
        __syncthreads();
        s ^= 1;
    }
#pragma unroll
    for (int kk = 0; kk < BK; kk++) {
        float4 a0 = *(float4*)&As[s][kk][tr];
        float4 a1 = *(float4*)&As[s][kk][tr + 4];
        float4 b0 = *(float4*)&Bs[s][kk][tc];
        float4 b1 = *(float4*)&Bs[s][kk][tc + 4];
        float a[8] = {a0.x,a0.y,a0.z,a0.w,a1.x,a1.y,a1.z,a1.w};
        float b[8] = {b0.x,b0.y,b0.z,b0.w,b1.x,b1.y,b1.z,b1.w};
#pragma unroll
        for (int i = 0; i < 8; i++)
#pragma unroll
            for (int j = 0; j < 8; j++) acc[i][j] += a[i] * b[j];
    }

#pragma unroll
    for (int i = 0; i < 8; i++) {
        float* cr = &C[(size_t)(q0 + tr + i) * SEQ + k0b + tc];
        *(float4*)cr = make_float4(acc[i][0]*scale, acc[i][1]*scale,
                                   acc[i][2]*scale, acc[i][3]*scale);
        *(float4*)(cr + 4) = make_float4(acc[i][4]*scale, acc[i][5]*scale,
                                         acc[i][6]*scale, acc[i][7]*scale);
    }
}

// ---------------- row softmax over k<=q, zeros beyond (in-place) ----------------
__global__ __launch_bounds__(256)
void softmax_causal(float* __restrict__ Sc) {
    const int r = blockIdx.x;             // r = h*SEQ + q
    const int q = r & (SEQ - 1);
    float* row = Sc + (size_t)r * SEQ;
    const int n = q + 1;
    const int tid = threadIdx.x;
    __shared__ float red[256];

    float m = -INFINITY;
    for (int j = tid; j < n; j += 256) m = fmaxf(m, row[j]);
    red[tid] = m; __syncthreads();
    for (int s = 128; s > 0; s >>= 1) {
        if (tid < s) red[tid] = fmaxf(red[tid], red[tid + s]);
        __syncthreads();
    }
    m = red[0]; __syncthreads();

    float sum = 0.f;
    for (int j = tid; j < n; j += 256) {
        float e = __expf(row[j] - m);
        row[j] = e;
        sum += e;
    }
    red[tid] = sum; __syncthreads();
    for (int s = 128; s > 0; s >>= 1) {
        if (tid < s) red[tid] += red[tid + s];
        __syncthreads();
    }
    const float inv = 1.f / red[0];
    for (int j = tid; j < n; j += 256) row[j] *= inv;
    for (int j = n + tid; j < SEQ; j += 256) row[j] = 0.f;
}

// ---------------- rms norm: one block per row ----------------
__global__ __launch_bounds__(256)
void rmsnorm(const float* __restrict__ X, float* __restrict__ Y,
             const float* __restrict__ W, int n, int ldx, int ldy) {
    const int r = blockIdx.x;
    const float* x = X + (size_t)r * ldx;
    float*       y = Y + (size_t)r * ldy;
    const int tid = threadIdx.x;
    __shared__ float red[256];

    float ss = 0.f;
    for (int j = tid; j < n; j += 256) { float v = x[j]; ss += v * v; }
    red[tid] = ss; __syncthreads();
    for (int s = 128; s > 0; s >>= 1) {
        if (tid < s) red[tid] += red[tid + s];
        __syncthreads();
    }
    const float rinv = rsqrtf(red[0] / (float)n + 1e-6f);
    for (int j = tid; j < n; j += 256) y[j] = x[j] * rinv * W[j];
}

// ---------------- RoPE + head gather: one block per sequence position ----------------
__global__ __launch_bounds__(256)
void rope_gather(const float* __restrict__ q,   // [SEQ, NH*DQK]
                 const float* __restrict__ kv,  // [SEQ, NKV*(DNOPE+DV)]
                 const float* __restrict__ ckv, // [SEQ, KVRANK+DROPE]
                 const float* __restrict__ cosT, const float* __restrict__ sinT,
                 const int* __restrict__ pos,   // int32 (JAX x64 disabled)
                 float* __restrict__ qf,        // [NH, SEQ, DQK]
                 float* __restrict__ kk,        // [NKV, SEQ, DQK]
                 float* __restrict__ vv) {      // [NKV, SEQ, DV]
    const int s = blockIdx.x;
    const int p = pos[s];
    const float* c  = cosT + (size_t)p * DROPE;
    const float* sn = sinT + (size_t)p * DROPE;

    for (int i = threadIdx.x; i < NH * DQK; i += 256) {
        int h = i / DQK, d = i % DQK;
        const float* qr = q + (size_t)s * NH * DQK + h * DQK;
        float val;
        if (d < DNOPE) val = qr[d];
        else {
            int dr = d - DNOPE;
            float x  = qr[d];
            float rh = (dr < DROPE / 2) ? -qr[DNOPE + dr + DROPE / 2]
                                        :  qr[DNOPE + dr - DROPE / 2];
            val = x * c[dr] + rh * sn[dr];
        }
        qf[((size_t)h * SEQ + s) * DQK + d] = val;
    }
    for (int i = threadIdx.x; i < NKV * DQK; i += 256) {
        int kh = i / DQK, d = i % DQK;
        float val;
        if (d < DNOPE) val = kv[(size_t)s * NKV * (DNOPE + DV) + kh * (DNOPE + DV) + d];
        else {
            int dr = d - DNOPE;
            const float* kr = ckv + (size_t)s * (KVRANK + DROPE) + KVRANK;
            float x  = kr[dr];
            float rh = (dr < DROPE / 2) ? -kr[dr + DROPE / 2] : kr[dr - DROPE / 2];
            val = x * c[dr] + rh * sn[dr];
        }
        kk[((size_t)kh * SEQ + s) * DQK + d] = val;
    }
    for (int i = threadIdx.x; i < NKV * DV; i += 256) {
        int kh = i / DV, d = i % DV;
        vv[((size_t)kh * SEQ + s) * DV + d] =
            kv[(size_t)s * NKV * (DNOPE + DV) + kh * (DNOPE + DV) + DNOPE + d];
    }
}

// ---------------- launch ----------------
extern "C" void kernel_launch(void* const* d_in, const int* in_sizes, int n_in,
                              void* d_out, int out_size) {
    const float* hidden    = (const float*)d_in[0];
    const float* cosT      = (const float*)d_in[1];
    const float* sinT      = (const float*)d_in[2];
    const float* wq_a      = (const float*)d_in[3];
    const float* q_a_ln_w  = (const float*)d_in[4];
    const float* wq_b      = (const float*)d_in[5];
    const float* wkv_a     = (const float*)d_in[6];
    const float* kv_a_ln_w = (const float*)d_in[7];
    const float* wkv_b     = (const float*)d_in[8];
    const float* wo        = (const float*)d_in[9];
    const int*   cpos      = (const int*)d_in[10];
    float* out = (float*)d_out;

    float *qa, *qan, *q, *ckv, *ckvn, *kv, *qf, *k, *v, *sc, *ao;
    cudaGetSymbolAddress((void**)&qa,   g_qa);
    cudaGetSymbolAddress((void**)&qan,  g_qan);
    cudaGetSymbolAddress((void**)&q,    g_q);
    cudaGetSymbolAddress((void**)&ckv,  g_ckv);
    cudaGetSymbolAddress((void**)&ckvn, g_ckvn);
    cudaGetSymbolAddress((void**)&kv,   g_kv);
    cudaGetSymbolAddress((void**)&qf,   g_qf);
    cudaGetSymbolAddress((void**)&k,    g_k);
    cudaGetSymbolAddress((void**)&v,    g_v);
    cudaGetSymbolAddress((void**)&sc,   g_sc);
    cudaGetSymbolAddress((void**)&ao,   g_ao);

    // 1) q_a = hidden @ wq_a          [2048,2048]x[2048,1536]
    sgemm128<0,false><<<dim3(QRANK/BN, SEQ/BM, 1), 256>>>(hidden, wq_a, qa,
        SEQ, QRANK, DM, DM, QRANK, QRANK, 0, 0, 0, 0);
    // 2) rmsnorm q_a
    rmsnorm<<<SEQ, 256>>>(qa, qan, q_a_ln_w, QRANK, QRANK, QRANK);
    // 3) q = qan @ wq_b               [2048,1536]x[1536,3072]
    sgemm128<0,false><<<dim3(NH*DQK/BN, SEQ/BM, 1), 256>>>(qan, wq_b, q,
        SEQ, NH*DQK, QRANK, QRANK, NH*DQK, NH*DQK, 0, 0, 0, 0);
    // 4) ckv = hidden @ wkv_a         [2048,2048]x[2048,576]  (N-guarded)
    sgemm128<0,true><<<dim3((KVRANK+DROPE+BN-1)/BN, SEQ/BM, 1), 256>>>(hidden, wkv_a, ckv,
        SEQ, KVRANK+DROPE, DM, DM, KVRANK+DROPE, KVRANK+DROPE, 0, 0, 0, 0);
    // 5) rmsnorm ckv[:, :512]
    rmsnorm<<<SEQ, 256>>>(ckv, ckvn, kv_a_ln_w, KVRANK, KVRANK+DROPE, KVRANK);
    // 6) kv = ckvn @ wkv_b            [2048,512]x[512,1024]
    sgemm128<0,false><<<dim3(NKV*(DNOPE+DV)/BN, SEQ/BM, 1), 256>>>(ckvn, wkv_b, kv,
        SEQ, NKV*(DNOPE+DV), KVRANK, KVRANK, NKV*(DNOPE+DV), NKV*(DNOPE+DV), 0, 0, 0, 0);
    // 7) RoPE + gather
    rope_gather<<<SEQ, 256>>>(q, kv, ckv, cosT, sinT, cpos, qf, k, v);
    // 8) scores (batched over heads, causal-skipped)
    scores128<<<dim3(SEQ/BN, SEQ/BM, NH), 256>>>(qf, k, sc, rsqrtf((float)DQK));
    // 9) causal softmax in place
    softmax_causal<<<NH * SEQ, 256>>>(sc);
    // 10) P @ V, batched over heads, causal-capped K
    sgemm128<1,false><<<dim3(DV/BN, SEQ/BM, NH), 256>>>(sc, v, ao,
        SEQ, DV, SEQ, SEQ, DV, NH*DV,
        (size_t)SEQ*SEQ, (size_t)SEQ*DV, (size_t)DV, 2);
    // 11) out = ao @ wo               [2048,2048]x[2048,2048]
    sgemm128<0,false><<<dim3(DM/BN, SEQ/BM, 1), 256>>>(ao, wo, out,
        SEQ, DM, NH*DV, NH*DV, DM, DM, 0, 0, 0, 0);
}

// round 7
// speedup vs baseline: 4.7293x; 1.2866x over previous
#include <cuda_runtime.h>
#include <cuda_bf16.h>
#include <math.h>

#define SEQ   2048
#define NH    16
#define NKV   4
#define DQK   192
#define DNOPE 128
#define DROPE 64
#define DV    128
#define DM    2048
#define QRANK 1536
#define KVRANK 512

// ---------------- scratch (static device globals; allocation-free) ----------------
__device__ float g_qa  [SEQ * QRANK];
__device__ float g_qan [SEQ * QRANK];
__device__ float g_q   [SEQ * NH * DQK];
__device__ float g_ckv [SEQ * (KVRANK + DROPE)];
__device__ float g_ckvn[SEQ * KVRANK];
__device__ float g_kv  [SEQ * NKV * (DNOPE + DV)];
__device__ float g_qf  [NH  * SEQ * DQK];
__device__ float g_k   [NKV * SEQ * DQK];
__device__ float g_v   [NKV * SEQ * DV];
__device__ float g_sc  [67108864];                    // NH*SEQ*SEQ
__device__ float g_ao  [SEQ * NH * DV];

// ---------------- tf32 helpers ----------------
__device__ __forceinline__ unsigned f2tf(float x) {
    unsigned u;
    asm("cvt.rna.tf32.f32 %0, %1;" : "=r"(u) : "f"(x));
    return u;
}
__device__ __forceinline__ void mma_tf32(float* c, const unsigned* a,
                                         unsigned b0, unsigned b1) {
    asm volatile("mma.sync.aligned.m16n8k8.row.col.f32.tf32.tf32.f32 "
        "{%0,%1,%2,%3}, {%4,%5,%6,%7}, {%8,%9}, {%0,%1,%2,%3};\n"
        : "+f"(c[0]), "+f"(c[1]), "+f"(c[2]), "+f"(c[3])
        : "r"(a[0]), "r"(a[1]), "r"(a[2]), "r"(a[3]), "r"(b0), "r"(b1));
}

// ================= 128x128x16 tf32 MMA GEMM (3xTF32 split) =====================
// BT: B given as [N,K] row-major (NT product).  KCAP: Keff=min(K,row0+128).
// NG: guard N (N=576).  CSKIP: skip tiles fully above causal diagonal.
// Batch: A += z*zA, B += (z>>zshiftB)*zB, C += z*zC.
template<bool BT, bool KCAP, bool NG, bool CSKIP>
__global__ __launch_bounds__(256)
void tgemm(const float* __restrict__ A, const float* __restrict__ B,
           float* __restrict__ C, int M, int N, int K,
           int lda, int ldb, int ldc, float scale,
           size_t zA, size_t zB, size_t zC, int zshiftB) {
    __shared__ __align__(16) float As[2][16][136];
    __shared__ __align__(16) float Bs[2][16][136];

    const int z = blockIdx.z;
    A += (size_t)z * zA;
    B += (size_t)(z >> zshiftB) * zB;
    C += (size_t)z * zC;

    const int row0 = blockIdx.y * 128;
    const int col0 = blockIdx.x * 128;
    if (CSKIP && col0 > row0 + 127) return;

    int Keff = K;
    if (KCAP) { int lim = row0 + 128; if (lim < Keff) Keff = lim; }

    const int tid = threadIdx.x;
    // A loader: row ar, cols ac..ac+7 (two float4), stored transposed
    const int ar = tid >> 1;
    const int ac = (tid & 1) * 8;
    // B loader (NN): row br (k), cols bc..bc+7
    const int br = tid >> 4;
    const int bc = (tid & 15) * 8;
    // B loader (BT, from [N,K]): n-row tn, k cols tk..tk+7, stored transposed
    const int tn = tid >> 1;
    const int tk = (tid & 1) * 8;

    const int lane = tid & 31;
    const int wid  = tid >> 5;
    const int wm = (wid & 3) * 32;    // warp m offset
    const int wn = (wid >> 2) * 64;   // warp n offset
    const int grp = lane >> 2, tig = lane & 3;

    float acc[2][8][4];
#pragma unroll
    for (int mt = 0; mt < 2; mt++)
#pragma unroll
        for (int nt = 0; nt < 8; nt++)
#pragma unroll
            for (int i = 0; i < 4; i++) acc[mt][nt][i] = 0.f;

    float4 pa0, pa1, pb0, pb1;

    auto loadA = [&](int k0) {
        const float* p = &A[(size_t)(row0 + ar) * lda + k0 + ac];
        pa0 = *(const float4*)p;
        pa1 = *(const float4*)(p + 4);
    };
    auto loadB = [&](int k0) {
        if (BT) {
            const float* p = &B[(size_t)(col0 + tn) * ldb + k0 + tk];
            pb0 = *(const float4*)p;
            pb1 = *(const float4*)(p + 4);
        } else {
            if (!NG || col0 + bc + 3 < N)
                pb0 = *(const float4*)&B[(size_t)(k0 + br) * ldb + col0 + bc];
            else pb0 = make_float4(0.f, 0.f, 0.f, 0.f);
            if (!NG || col0 + bc + 7 < N)
                pb1 = *(const float4*)&B[(size_t)(k0 + br) * ldb + col0 + bc + 4];
            else pb1 = make_float4(0.f, 0.f, 0.f, 0.f);
        }
    };
    auto stage = [&](int s) {
#pragma unroll
        for (int j = 0; j < 4; j++) As[s][ac + j][ar]     = (&pa0.x)[j];
#pragma unroll
        for (int j = 0; j < 4; j++) As[s][ac + 4 + j][ar] = (&pa1.x)[j];
        if (BT) {
#pragma unroll
            for (int j = 0; j < 4; j++) Bs[s][tk + j][tn]     = (&pb0.x)[j];
#pragma unroll
            for (int j = 0; j < 4; j++) Bs[s][tk + 4 + j][tn] = (&pb1.x)[j];
        } else {
            *(float4*)&Bs[s][br][bc]     = pb0;
            *(float4*)&Bs[s][br][bc + 4] = pb1;
        }
    };
    auto compute = [&](int s) {
#pragma unroll
        for (int k8 = 0; k8 < 16; k8 += 8) {
            unsigned ah[2][4], al[2][4];
#pragma unroll
            for (int mt = 0; mt < 2; mt++) {
                int r = wm + mt * 16 + grp;
                float x0 = As[s][k8 + tig][r];
                float x1 = As[s][k8 + tig][r + 8];
                float x2 = As[s][k8 + tig + 4][r];
                float x3 = As[s][k8 + tig + 4][r + 8];
                ah[mt][0] = f2tf(x0); al[mt][0] = f2tf(x0 - __uint_as_float(ah[mt][0]));
                ah[mt][1] = f2tf(x1); al[mt][1] = f2tf(x1 - __uint_as_float(ah[mt][1]));
                ah[mt][2] = f2tf(x2); al[mt][2] = f2tf(x2 - __uint_as_float(ah[mt][2]));
                ah[mt][3] = f2tf(x3); al[mt][3] = f2tf(x3 - __uint_as_float(ah[mt][3]));
            }
#pragma unroll
            for (int nt = 0; nt < 8; nt++) {
                int cc = wn + nt * 8 + grp;
                float y0 = Bs[s][k8 + tig][cc];
                float y1 = Bs[s][k8 + tig + 4][cc];
                unsigned bh0 = f2tf(y0), bh1 = f2tf(y1);
                unsigned bl0 = f2tf(y0 - __uint_as_float(bh0));
                unsigned bl1 = f2tf(y1 - __uint_as_float(bh1));
#pragma unroll
                for (int mt = 0; mt < 2; mt++) {
                    mma_tf32(acc[mt][nt], ah[mt], bh0, bh1);
                    mma_tf32(acc[mt][nt], al[mt], bh0, bh1);
                    mma_tf32(acc[mt][nt], ah[mt], bl0, bl1);
                }
            }
        }
    };

    // prologue
    loadA(0); loadB(0); stage(0);
    __syncthreads();
    int s = 0;
    for (int k0 = 16; k0 < Keff; k0 += 16) {
        loadA(k0); loadB(k0);
        compute(s);
        stage(s ^ 1);
        __syncthreads();
        s ^= 1;
    }
    compute(s);

    // epilogue
#pragma unroll
    for (int mt = 0; mt < 2; mt++) {
#pragma unroll
        for (int nt = 0; nt < 8; nt++) {
            int r = row0 + wm + mt * 16 + grp;
            int c = col0 + wn + nt * 8 + 2 * tig;
            if (!NG || c < N) {
                *(float2*)&C[(size_t)r * ldc + c] =
                    make_float2(acc[mt][nt][0] * scale, acc[mt][nt][1] * scale);
                *(float2*)&C[(size_t)(r + 8) * ldc + c] =
                    make_float2(acc[mt][nt][2] * scale, acc[mt][nt][3] * scale);
            }
        }
    }
}

// ---------------- row softmax over k<=q, zeros beyond (in-place) ----------------
__global__ __launch_bounds__(256)
void softmax_causal(float* __restrict__ Sc) {
    const int r = blockIdx.x;             // r = h*SEQ + q
    const int q = r & (SEQ - 1);
    float* row = Sc + (size_t)r * SEQ;
    const int n = q + 1;
    const int tid = threadIdx.x;
    __shared__ float red[256];

    float m = -INFINITY;
    for (int j = tid; j < n; j += 256) m = fmaxf(m, row[j]);
    red[tid] = m; __syncthreads();
    for (int s = 128; s > 0; s >>= 1) {
        if (tid < s) red[tid] = fmaxf(red[tid], red[tid + s]);
        __syncthreads();
    }
    m = red[0]; __syncthreads();

    float sum = 0.f;
    for (int j = tid; j < n; j += 256) {
        float e = __expf(row[j] - m);
        row[j] = e;
        sum += e;
    }
    red[tid] = sum; __syncthreads();
    for (int s = 128; s > 0; s >>= 1) {
        if (tid < s) red[tid] += red[tid + s];
        __syncthreads();
    }
    const float inv = 1.f / red[0];
    for (int j = tid; j < n; j += 256) row[j] *= inv;
    for (int j = n + tid; j < SEQ; j += 256) row[j] = 0.f;
}

// ---------------- rms norm: one block per row ----------------
__global__ __launch_bounds__(256)
void rmsnorm(const float* __restrict__ X, float* __restrict__ Y,
             const float* __restrict__ W, int n, int ldx, int ldy) {
    const int r = blockIdx.x;
    const float* x = X + (size_t)r * ldx;
    float*       y = Y + (size_t)r * ldy;
    const int tid = threadIdx.x;
    __shared__ float red[256];

    float ss = 0.f;
    for (int j = tid; j < n; j += 256) { float v = x[j]; ss += v * v; }
    red[tid] = ss; __syncthreads();
    for (int s = 128; s > 0; s >>= 1) {
        if (tid < s) red[tid] += red[tid + s];
        __syncthreads();
    }
    const float rinv = rsqrtf(red[0] / (float)n + 1e-6f);
    for (int j = tid; j < n; j += 256) y[j] = x[j] * rinv * W[j];
}

// ---------------- RoPE + head gather: one block per sequence position ----------------
__global__ __launch_bounds__(256)
void rope_gather(const float* __restrict__ q,   // [SEQ, NH*DQK]
                 const float* __restrict__ kv,  // [SEQ, NKV*(DNOPE+DV)]
                 const float* __restrict__ ckv, // [SEQ, KVRANK+DROPE]
                 const float* __restrict__ cosT, const float* __restrict__ sinT,
                 const int* __restrict__ pos,   // int32 (JAX x64 disabled)
                 float* __restrict__ qf,        // [NH, SEQ, DQK]
                 float* __restrict__ kk,        // [NKV, SEQ, DQK]
                 float* __restrict__ vv) {      // [NKV, SEQ, DV]
    const int s = blockIdx.x;
    const int p = pos[s];
    const float* c  = cosT + (size_t)p * DROPE;
    const float* sn = sinT + (size_t)p * DROPE;

    for (int i = threadIdx.x; i < NH * DQK; i += 256) {
        int h = i / DQK, d = i % DQK;
        const float* qr = q + (size_t)s * NH * DQK + h * DQK;
        float val;
        if (d < DNOPE) val = qr[d];
        else {
            int dr = d - DNOPE;
            float x  = qr[d];
            float rh = (dr < DROPE / 2) ? -qr[DNOPE + dr + DROPE / 2]
                                        :  qr[DNOPE + dr - DROPE / 2];
            val = x * c[dr] + rh * sn[dr];
        }
        qf[((size_t)h * SEQ + s) * DQK + d] = val;
    }
    for (int i = threadIdx.x; i < NKV * DQK; i += 256) {
        int kh = i / DQK, d = i % DQK;
        float val;
        if (d < DNOPE) val = kv[(size_t)s * NKV * (DNOPE + DV) + kh * (DNOPE + DV) + d];
        else {
            int dr = d - DNOPE;
            const float* kr = ckv + (size_t)s * (KVRANK + DROPE) + KVRANK;
            float x  = kr[dr];
            float rh = (dr < DROPE / 2) ? -kr[dr + DROPE / 2] : kr[dr - DROPE / 2];
            val = x * c[dr] + rh * sn[dr];
        }
        kk[((size_t)kh * SEQ + s) * DQK + d] = val;
    }
    for (int i = threadIdx.x; i < NKV * DV; i += 256) {
        int kh = i / DV, d = i % DV;
        vv[((size_t)kh * SEQ + s) * DV + d] =
            kv[(size_t)s * NKV * (DNOPE + DV) + kh * (DNOPE + DV) + DNOPE + d];
    }
}

// ---------------- launch ----------------
extern "C" void kernel_launch(void* const* d_in, const int* in_sizes, int n_in,
                              void* d_out, int out_size) {
    const float* hidden    = (const float*)d_in[0];
    const float* cosT      = (const float*)d_in[1];
    const float* sinT      = (const float*)d_in[2];
    const float* wq_a      = (const float*)d_in[3];
    const float* q_a_ln_w  = (const float*)d_in[4];
    const float* wq_b      = (const float*)d_in[5];
    const float* wkv_a     = (const float*)d_in[6];
    const float* kv_a_ln_w = (const float*)d_in[7];
    const float* wkv_b     = (const float*)d_in[8];
    const float* wo        = (const float*)d_in[9];
    const int*   cpos      = (const int*)d_in[10];
    float* out = (float*)d_out;

    float *qa, *qan, *q, *ckv, *ckvn, *kv, *qf, *k, *v, *sc, *ao;
    cudaGetSymbolAddress((void**)&qa,   g_qa);
    cudaGetSymbolAddress((void**)&qan,  g_qan);
    cudaGetSymbolAddress((void**)&q,    g_q);
    cudaGetSymbolAddress((void**)&ckv,  g_ckv);
    cudaGetSymbolAddress((void**)&ckvn, g_ckvn);
    cudaGetSymbolAddress((void**)&kv,   g_kv);
    cudaGetSymbolAddress((void**)&qf,   g_qf);
    cudaGetSymbolAddress((void**)&k,    g_k);
    cudaGetSymbolAddress((void**)&v,    g_v);
    cudaGetSymbolAddress((void**)&sc,   g_sc);
    cudaGetSymbolAddress((void**)&ao,   g_ao);

    // 1) q_a = hidden @ wq_a          [2048,2048]x[2048,1536]
    tgemm<false,false,false,false><<<dim3(QRANK/128, SEQ/128, 1), 256>>>(
        hidden, wq_a, qa, SEQ, QRANK, DM, DM, QRANK, QRANK, 1.f, 0, 0, 0, 0);
    // 2) rmsnorm q_a
    rmsnorm<<<SEQ, 256>>>(qa, qan, q_a_ln_w, QRANK, QRANK, QRANK);
    // 3) q = qan @ wq_b               [2048,1536]x[1536,3072]
    tgemm<false,false,false,false><<<dim3(NH*DQK/128, SEQ/128, 1), 256>>>(
        qan, wq_b, q, SEQ, NH*DQK, QRANK, QRANK, NH*DQK, NH*DQK, 1.f, 0, 0, 0, 0);
    // 4) ckv = hidden @ wkv_a         [2048,2048]x[2048,576]  (N-guarded)
    tgemm<false,false,true,false><<<dim3((KVRANK+DROPE+127)/128, SEQ/128, 1), 256>>>(
        hidden, wkv_a, ckv, SEQ, KVRANK+DROPE, DM, DM, KVRANK+DROPE, KVRANK+DROPE,
        1.f, 0, 0, 0, 0);
    // 5) rmsnorm ckv[:, :512]
    rmsnorm<<<SEQ, 256>>>(ckv, ckvn, kv_a_ln_w, KVRANK, KVRANK+DROPE, KVRANK);
    // 6) kv = ckvn @ wkv_b            [2048,512]x[512,1024]
    tgemm<false,false,false,false><<<dim3(NKV*(DNOPE+DV)/128, SEQ/128, 1), 256>>>(
        ckvn, wkv_b, kv, SEQ, NKV*(DNOPE+DV), KVRANK, KVRANK, NKV*(DNOPE+DV),
        NKV*(DNOPE+DV), 1.f, 0, 0, 0, 0);
    // 7) RoPE + gather
    rope_gather<<<SEQ, 256>>>(q, kv, ckv, cosT, sinT, cpos, qf, k, v);
    // 8) scores = scale * Qf @ K^T (batched over heads, causal-skipped)
    tgemm<true,false,false,true><<<dim3(SEQ/128, SEQ/128, NH), 256>>>(
        qf, k, sc, SEQ, SEQ, DQK, DQK, DQK, SEQ, rsqrtf((float)DQK),
        (size_t)SEQ*DQK, (size_t)SEQ*DQK, (size_t)SEQ*SEQ, 2);
    // 9) causal softmax in place
    softmax_causal<<<NH * SEQ, 256>>>(sc);
    // 10) P @ V, batched over heads, causal-capped K
    tgemm<false,true,false,false><<<dim3(1, SEQ/128, NH), 256>>>(
        sc, v, ao, SEQ, DV, SEQ, SEQ, DV, NH*DV, 1.f,
        (size_t)SEQ*SEQ, (size_t)SEQ*DV, (size_t)DV, 2);
    // 11) out = ao @ wo               [2048,2048]x[2048,2048]
    tgemm<false,false,false,false><<<dim3(DM/128, SEQ/128, 1), 256>>>(
        ao, wo, out, SEQ, DM, NH*DV, NH*DV, DM, DM, 1.f, 0, 0, 0, 0);
}

// round 10
// speedup vs baseline: 7.0542x; 1.4916x over previous
#include <cuda_runtime.h>
#include <cuda_bf16.h>
#include <math.h>
#include <stdint.h>

#define SEQ   2048
#define NH    16
#define NKV   4
#define DQK   192
#define DNOPE 128
#define DROPE 64
#define DV    128
#define DM    2048
#define QRANK 1536
#define KVRANK 512

// ---------------- scratch (static device globals; allocation-free) ----------------
__device__ float g_qa  [SEQ * QRANK];
__device__ float g_qan [SEQ * QRANK];
__device__ float g_q   [SEQ * NH * DQK];
__device__ float g_ckv [SEQ * (KVRANK + DROPE)];
__device__ float g_ckvn[SEQ * KVRANK];
__device__ float g_kv  [SEQ * NKV * (DNOPE + DV)];
__device__ float g_qf  [NH  * SEQ * DQK];
__device__ float g_k   [NKV * SEQ * DQK];
__device__ float g_v   [NKV * SEQ * DV];
__device__ float g_sc  [67108864];                    // NH*SEQ*SEQ
__device__ float g_ao  [SEQ * NH * DV];

// ---------------- helpers ----------------
__device__ __forceinline__ uint32_t s2u(const void* p) {
    uint32_t a;
    asm("{ .reg .u64 t; cvta.to.shared.u64 t, %1; cvt.u32.u64 %0, t; }"
        : "=r"(a) : "l"(p));
    return a;
}
__device__ __forceinline__ uint32_t pk(__nv_bfloat16 a, __nv_bfloat16 b) {
    unsigned short ua = *(unsigned short*)&a, ub = *(unsigned short*)&b;
    return (uint32_t)ua | ((uint32_t)ub << 16);
}
__device__ __forceinline__ void bsplit(float x, __nv_bfloat16& h, __nv_bfloat16& l) {
    h = __float2bfloat16_rn(x);
    l = __float2bfloat16_rn(x - __bfloat162float(h));
}
__device__ __forceinline__ void ldm4(uint32_t* r, uint32_t addr) {
    asm volatile("ldmatrix.sync.aligned.m8n8.x4.shared.b16 {%0,%1,%2,%3}, [%4];"
        : "=r"(r[0]), "=r"(r[1]), "=r"(r[2]), "=r"(r[3]) : "r"(addr));
}
__device__ __forceinline__ void mma_bf16(float* c, const uint32_t* a,
                                         uint32_t b0, uint32_t b1) {
    asm volatile("mma.sync.aligned.m16n8k16.row.col.f32.bf16.bf16.f32 "
        "{%0,%1,%2,%3}, {%4,%5,%6,%7}, {%8,%9}, {%0,%1,%2,%3};\n"
        : "+f"(c[0]), "+f"(c[1]), "+f"(c[2]), "+f"(c[3])
        : "r"(a[0]), "r"(a[1]), "r"(a[2]), "r"(a[3]), "r"(b0), "r"(b1));
}

// =========== 128x128x32 bf16 hi/lo split GEMM (3-pass), ldmatrix+mma ===========
// BT: B given [N,K] row-major (NT).  KCAP: Keff=min(K,row0+128).
// NG: guard N.  CSKIP: skip tiles above causal diagonal.
// Batch: A += z*zA, B += (z>>zshiftB)*zB, C += z*zC.
// Dynamic smem: 2 buffers x {Ah,Al,Bh,Bl}, each 128 rows x 40 bf16 (stride pad).
#define SPAD 40
#define BUFB 40960           // bytes per buffer (4 * 128*40*2)
#define OFF_AL 10240
#define OFF_BH 20480
#define OFF_BL 30720

template<bool BT, bool KCAP, bool NG, bool CSKIP>
__global__ __launch_bounds__(256)
void bgemm(const float* __restrict__ A, const float* __restrict__ B,
           float* __restrict__ C, int M, int N, int K,
           int lda, int ldb, int ldc, float scale,
           size_t zA, size_t zB, size_t zC, int zshiftB) {
    extern __shared__ __align__(16) char smem[];

    const int z = blockIdx.z;
    A += (size_t)z * zA;
    B += (size_t)(z >> zshiftB) * zB;
    C += (size_t)z * zC;

    const int row0 = blockIdx.y * 128;
    const int col0 = blockIdx.x * 128;
    if (CSKIP && col0 > row0 + 127) return;

    int Keff = K;
    if (KCAP) { int lim = row0 + 128; if (lim < Keff) Keff = lim; }
    const int iters = Keff >> 5;

    const int tid  = threadIdx.x;
    const int lane = tid & 31;
    const int wid  = tid >> 5;
    const uint32_t sbase = s2u(smem);

    // staging mapping: one thread = one row, 16 k-elems
    const int sr = tid >> 1;            // 0..127
    const int sk = (tid & 1) * 16;      // 0 or 16

    // compute mapping
    const int wm = (wid & 3) * 32;
    const int wn = (wid >> 2) * 64;

    float acc[2][8][4];
#pragma unroll
    for (int mt = 0; mt < 2; mt++)
#pragma unroll
        for (int nt = 0; nt < 8; nt++)
#pragma unroll
            for (int i = 0; i < 4; i++) acc[mt][nt][i] = 0.f;

    float av[16], bv[16];

    auto loadG = [&](int k0) {
        const float* ap = A + (size_t)(row0 + sr) * lda + k0 + sk;
        *(float4*)(av)      = *(const float4*)(ap);
        *(float4*)(av + 4)  = *(const float4*)(ap + 4);
        *(float4*)(av + 8)  = *(const float4*)(ap + 8);
        *(float4*)(av + 12) = *(const float4*)(ap + 12);
        if (BT) {
            const float* bp = B + (size_t)(col0 + sr) * ldb + k0 + sk;
            *(float4*)(bv)      = *(const float4*)(bp);
            *(float4*)(bv + 4)  = *(const float4*)(bp + 4);
            *(float4*)(bv + 8)  = *(const float4*)(bp + 8);
            *(float4*)(bv + 12) = *(const float4*)(bp + 12);
        } else {
            if (!NG || col0 + sr < N) {
                const float* bp = B + (size_t)(k0 + sk) * ldb + col0 + sr;
#pragma unroll
                for (int i = 0; i < 16; i++) bv[i] = bp[(size_t)i * ldb];
            } else {
#pragma unroll
                for (int i = 0; i < 16; i++) bv[i] = 0.f;
            }
        }
    };
    auto stage = [&](int buf) {
        __nv_bfloat16 h[16], l[16];
#pragma unroll
        for (int i = 0; i < 16; i++) bsplit(av[i], h[i], l[i]);
        uint32_t off = (uint32_t)buf * BUFB + ((uint32_t)sr * SPAD + sk) * 2;
        *(uint4*)(smem + off) = make_uint4(pk(h[0],h[1]), pk(h[2],h[3]),
                                           pk(h[4],h[5]), pk(h[6],h[7]));
        *(uint4*)(smem + off + 16) = make_uint4(pk(h[8],h[9]), pk(h[10],h[11]),
                                                pk(h[12],h[13]), pk(h[14],h[15]));
        *(uint4*)(smem + off + OFF_AL) = make_uint4(pk(l[0],l[1]), pk(l[2],l[3]),
                                                    pk(l[4],l[5]), pk(l[6],l[7]));
        *(uint4*)(smem + off + OFF_AL + 16) = make_uint4(pk(l[8],l[9]), pk(l[10],l[11]),
                                                         pk(l[12],l[13]), pk(l[14],l[15]));
#pragma unroll
        for (int i = 0; i < 16; i++) bsplit(bv[i], h[i], l[i]);
        *(uint4*)(smem + off + OFF_BH) = make_uint4(pk(h[0],h[1]), pk(h[2],h[3]),
                                                    pk(h[4],h[5]), pk(h[6],h[7]));
        *(uint4*)(smem + off + OFF_BH + 16) = make_uint4(pk(h[8],h[9]), pk(h[10],h[11]),
                                                         pk(h[12],h[13]), pk(h[14],h[15]));
        *(uint4*)(smem + off + OFF_BL) = make_uint4(pk(l[0],l[1]), pk(l[2],l[3]),
                                                    pk(l[4],l[5]), pk(l[6],l[7]));
        *(uint4*)(smem + off + OFF_BL + 16) = make_uint4(pk(l[8],l[9]), pk(l[10],l[11]),
                                                         pk(l[12],l[13]), pk(l[14],l[15]));
    };
    auto compute = [&](int buf) {
        const uint32_t ba = sbase + (uint32_t)buf * BUFB;
#pragma unroll
        for (int s16 = 0; s16 < 32; s16 += 16) {
            uint32_t ah[2][4], al[2][4];
#pragma unroll
            for (int mt = 0; mt < 2; mt++) {
                uint32_t addr = ba + (((uint32_t)(wm + mt * 16 + (lane & 15))) * SPAD
                                      + s16 + ((lane >> 4) << 3)) * 2;
                ldm4(ah[mt], addr);
                ldm4(al[mt], addr + OFF_AL);
            }
#pragma unroll
            for (int p = 0; p < 4; p++) {
                const int g = lane >> 3;
                uint32_t addr = ba + OFF_BH +
                    (((uint32_t)(wn + p * 16 + (lane & 7) + ((g >> 1) << 3))) * SPAD
                     + s16 + ((g & 1) << 3)) * 2;
                uint32_t bh[4], bl[4];
                ldm4(bh, addr);
                ldm4(bl, addr + (OFF_BL - OFF_BH));
#pragma unroll
                for (int mt = 0; mt < 2; mt++) {
                    mma_bf16(acc[mt][2*p],   ah[mt], bh[0], bh[1]);
                    mma_bf16(acc[mt][2*p],   al[mt], bh[0], bh[1]);
                    mma_bf16(acc[mt][2*p],   ah[mt], bl[0], bl[1]);
                    mma_bf16(acc[mt][2*p+1], ah[mt], bh[2], bh[3]);
                    mma_bf16(acc[mt][2*p+1], al[mt], bh[2], bh[3]);
                    mma_bf16(acc[mt][2*p+1], ah[mt], bl[2], bl[3]);
                }
            }
        }
    };

    // prologue
    loadG(0);
    stage(0);
    __syncthreads();

    for (int it = 0; it < iters; ++it) {
        const bool has = (it + 1) < iters;
        if (has) loadG((it + 1) << 5);
        compute(it & 1);
        if (has) stage((it + 1) & 1);
        __syncthreads();
    }

    // epilogue
    const int grp = lane >> 2, tig = lane & 3;
#pragma unroll
    for (int mt = 0; mt < 2; mt++) {
#pragma unroll
        for (int nt = 0; nt < 8; nt++) {
            int r = row0 + wm + mt * 16 + grp;
            int c = col0 + wn + nt * 8 + 2 * tig;
            if (!NG || c < N) {
                *(float2*)&C[(size_t)r * ldc + c] =
                    make_float2(acc[mt][nt][0] * scale, acc[mt][nt][1] * scale);
                *(float2*)&C[(size_t)(r + 8) * ldc + c] =
                    make_float2(acc[mt][nt][2] * scale, acc[mt][nt][3] * scale);
            }
        }
    }
}

// ---------------- row softmax over k<=q, zeros beyond (in-place) ----------------
__global__ __launch_bounds__(256)
void softmax_causal(float* __restrict__ Sc) {
    const int r = blockIdx.x;
    const int q = r & (SEQ - 1);
    float* row = Sc + (size_t)r * SEQ;
    const int n = q + 1;
    const int tid = threadIdx.x;
    __shared__ float red[256];

    float m = -INFINITY;
    for (int j = tid; j < n; j += 256) m = fmaxf(m, row[j]);
    red[tid] = m; __syncthreads();
    for (int s = 128; s > 0; s >>= 1) {
        if (tid < s) red[tid] = fmaxf(red[tid], red[tid + s]);
        __syncthreads();
    }
    m = red[0]; __syncthreads();

    float sum = 0.f;
    for (int j = tid; j < n; j += 256) {
        float e = __expf(row[j] - m);
        row[j] = e;
        sum += e;
    }
    red[tid] = sum; __syncthreads();
    for (int s = 128; s > 0; s >>= 1) {
        if (tid < s) red[tid] += red[tid + s];
        __syncthreads();
    }
    const float inv = 1.f / red[0];
    for (int j = tid; j < n; j += 256) row[j] *= inv;
    for (int j = n + tid; j < SEQ; j += 256) row[j] = 0.f;
}

// ---------------- rms norm: one block per row ----------------
__global__ __launch_bounds__(256)
void rmsnorm(const float* __restrict__ X, float* __restrict__ Y,
             const float* __restrict__ W, int n, int ldx, int ldy) {
    const int r = blockIdx.x;
    const float* x = X + (size_t)r * ldx;
    float*       y = Y + (size_t)r * ldy;
    const int tid = threadIdx.x;
    __shared__ float red[256];

    float ss = 0.f;
    for (int j = tid; j < n; j += 256) { float v = x[j]; ss += v * v; }
    red[tid] = ss; __syncthreads();
    for (int s = 128; s > 0; s >>= 1) {
        if (tid < s) red[tid] += red[tid + s];
        __syncthreads();
    }
    const float rinv = rsqrtf(red[0] / (float)n + 1e-6f);
    for (int j = tid; j < n; j += 256) y[j] = x[j] * rinv * W[j];
}

// ---------------- RoPE + head gather ----------------
__global__ __launch_bounds__(256)
void rope_gather(const float* __restrict__ q,
                 const float* __restrict__ kv,
                 const float* __restrict__ ckv,
                 const float* __restrict__ cosT, const float* __restrict__ sinT,
                 const int* __restrict__ pos,
                 float* __restrict__ qf,
                 float* __restrict__ kk,
                 float* __restrict__ vv) {
    const int s = blockIdx.x;
    const int p = pos[s];
    const float* c  = cosT + (size_t)p * DROPE;
    const float* sn = sinT + (size_t)p * DROPE;

    for (int i = threadIdx.x; i < NH * DQK; i += 256) {
        int h = i / DQK, d = i % DQK;
        const float* qr = q + (size_t)s * NH * DQK + h * DQK;
        float val;
        if (d < DNOPE) val = qr[d];
        else {
            int dr = d - DNOPE;
            float x  = qr[d];
            float rh = (dr < DROPE / 2) ? -qr[DNOPE + dr + DROPE / 2]
                                        :  qr[DNOPE + dr - DROPE / 2];
            val = x * c[dr] + rh * sn[dr];
        }
        qf[((size_t)h * SEQ + s) * DQK + d] = val;
    }
    for (int i = threadIdx.x; i < NKV * DQK; i += 256) {
        int kh = i / DQK, d = i % DQK;
        float val;
        if (d < DNOPE) val = kv[(size_t)s * NKV * (DNOPE + DV) + kh * (DNOPE + DV) + d];
        else {
            int dr = d - DNOPE;
            const float* kr = ckv + (size_t)s * (KVRANK + DROPE) + KVRANK;
            float x  = kr[dr];
            float rh = (dr < DROPE / 2) ? -kr[dr + DROPE / 2] : kr[dr - DROPE / 2];
            val = x * c[dr] + rh * sn[dr];
        }
        kk[((size_t)kh * SEQ + s) * DQK + d] = val;
    }
    for (int i = threadIdx.x; i < NKV * DV; i += 256) {
        int kh = i / DV, d = i % DV;
        vv[((size_t)kh * SEQ + s) * DV + d] =
            kv[(size_t)s * NKV * (DNOPE + DV) + kh * (DNOPE + DV) + DNOPE + d];
    }
}

// ---------------- launch ----------------
#define DSMEM (2 * BUFB)

extern "C" void kernel_launch(void* const* d_in, const int* in_sizes, int n_in,
                              void* d_out, int out_size) {
    const float* hidden    = (const float*)d_in[0];
    const float* cosT      = (const float*)d_in[1];
    const float* sinT      = (const float*)d_in[2];
    const float* wq_a      = (const float*)d_in[3];
    const float* q_a_ln_w  = (const float*)d_in[4];
    const float* wq_b      = (const float*)d_in[5];
    const float* wkv_a     = (const float*)d_in[6];
    const float* kv_a_ln_w = (const float*)d_in[7];
    const float* wkv_b     = (const float*)d_in[8];
    const float* wo        = (const float*)d_in[9];
    const int*   cpos      = (const int*)d_in[10];
    float* out = (float*)d_out;

    float *qa, *qan, *q, *ckv, *ckvn, *kv, *qf, *k, *v, *sc, *ao;
    cudaGetSymbolAddress((void**)&qa,   g_qa);
    cudaGetSymbolAddress((void**)&qan,  g_qan);
    cudaGetSymbolAddress((void**)&q,    g_q);
    cudaGetSymbolAddress((void**)&ckv,  g_ckv);
    cudaGetSymbolAddress((void**)&ckvn, g_ckvn);
    cudaGetSymbolAddress((void**)&kv,   g_kv);
    cudaGetSymbolAddress((void**)&qf,   g_qf);
    cudaGetSymbolAddress((void**)&k,    g_k);
    cudaGetSymbolAddress((void**)&v,    g_v);
    cudaGetSymbolAddress((void**)&sc,   g_sc);
    cudaGetSymbolAddress((void**)&ao,   g_ao);

    cudaFuncSetAttribute(bgemm<false,false,false,false>,
        cudaFuncAttributeMaxDynamicSharedMemorySize, DSMEM);
    cudaFuncSetAttribute(bgemm<false,false,true,false>,
        cudaFuncAttributeMaxDynamicSharedMemorySize, DSMEM);
    cudaFuncSetAttribute(bgemm<true,false,false,true>,
        cudaFuncAttributeMaxDynamicSharedMemorySize, DSMEM);
    cudaFuncSetAttribute(bgemm<false,true,false,false>,
        cudaFuncAttributeMaxDynamicSharedMemorySize, DSMEM);

    // 1) q_a = hidden @ wq_a          [2048,2048]x[2048,1536]
    bgemm<false,false,false,false><<<dim3(QRANK/128, SEQ/128, 1), 256, DSMEM>>>(
        hidden, wq_a, qa, SEQ, QRANK, DM, DM, QRANK, QRANK, 1.f, 0, 0, 0, 0);
    // 2) rmsnorm q_a
    rmsnorm<<<SEQ, 256>>>(qa, qan, q_a_ln_w, QRANK, QRANK, QRANK);
    // 3) q = qan @ wq_b               [2048,1536]x[1536,3072]
    bgemm<false,false,false,false><<<dim3(NH*DQK/128, SEQ/128, 1), 256, DSMEM>>>(
        qan, wq_b, q, SEQ, NH*DQK, QRANK, QRANK, NH*DQK, NH*DQK, 1.f, 0, 0, 0, 0);
    // 4) ckv = hidden @ wkv_a         [2048,2048]x[2048,576]  (N guard)
    bgemm<false,false,true,false><<<dim3((KVRANK+DROPE+127)/128, SEQ/128, 1), 256, DSMEM>>>(
        hidden, wkv_a, ckv, SEQ, KVRANK+DROPE, DM, DM, KVRANK+DROPE, KVRANK+DROPE,
        1.f, 0, 0, 0, 0);
    // 5) rmsnorm ckv[:, :512]
    rmsnorm<<<SEQ, 256>>>(ckv, ckvn, kv_a_ln_w, KVRANK, KVRANK+DROPE, KVRANK);
    // 6) kv = ckvn @ wkv_b            [2048,512]x[512,1024]
    bgemm<false,false,false,false><<<dim3(NKV*(DNOPE+DV)/128, SEQ/128, 1), 256, DSMEM>>>(
        ckvn, wkv_b, kv, SEQ, NKV*(DNOPE+DV), KVRANK, KVRANK, NKV*(DNOPE+DV),
        NKV*(DNOPE+DV), 1.f, 0, 0, 0, 0);
    // 7) RoPE + gather
    rope_gather<<<SEQ, 256>>>(q, kv, ckv, cosT, sinT, cpos, qf, k, v);
    // 8) scores = scale * Qf @ K^T (batched over heads, causal-skipped)
    // K is [NKV,SEQ,DQK] but DQK=192 is a multiple of 32; lda/ldb = DQK
    bgemm<true,false,false,true><<<dim3(SEQ/128, SEQ/128, NH), 256, DSMEM>>>(
        qf, k, sc, SEQ, SEQ, DQK, DQK, DQK, SEQ, rsqrtf((float)DQK),
        (size_t)SEQ*DQK, (size_t)SEQ*DQK, (size_t)SEQ*SEQ, 2);
    // 9) causal softmax in place
    softmax_causal<<<NH * SEQ, 256>>>(sc);
    // 10) P @ V, batched over heads, causal-capped K
    bgemm<false,true,false,false><<<dim3(1, SEQ/128, NH), 256, DSMEM>>>(
        sc, v, ao, SEQ, DV, SEQ, SEQ, DV, NH*DV, 1.f,
        (size_t)SEQ*SEQ, (size_t)SEQ*DV, (size_t)DV, 2);
    // 11) out = ao @ wo               [2048,2048]x[2048,2048]
    bgemm<false,false,false,false><<<dim3(DM/128, SEQ/128, 1), 256, DSMEM>>>(
        ao, wo, out, SEQ, DM, NH*DV, NH*DV, DM, DM, 1.f, 0, 0, 0, 0);
}

// round 11
// speedup vs baseline: 8.9353x; 1.2667x over previous
#include <cuda_runtime.h>
#include <cuda_bf16.h>
#include <math.h>
#include <stdint.h>

#define SEQ   2048
#define NH    16
#define NKV   4
#define DQK   192
#define DNOPE 128
#define DROPE 64
#define DV    128
#define DM    2048
#define QRANK 1536
#define KVRANK 512
#define KVAN  640         // padded N for wkv_a (576 -> 640)

typedef __nv_bfloat16 bf16;

// ---------------- scratch (static device globals; allocation-free) ----------------
__device__ float g_qa  [SEQ * QRANK];
__device__ float g_q   [SEQ * NH * DQK];
__device__ float g_ckv [SEQ * (KVRANK + DROPE)];
__device__ float g_kv  [SEQ * NKV * (DNOPE + DV)];
__device__ float g_sc  [67108864];                    // NH*SEQ*SEQ fp32 scores

__device__ bf16 g_hid_h [SEQ * DM],       g_hid_l [SEQ * DM];
__device__ bf16 g_qan_h [SEQ * QRANK],    g_qan_l [SEQ * QRANK];
__device__ bf16 g_ckvn_h[SEQ * KVRANK],   g_ckvn_l[SEQ * KVRANK];
__device__ bf16 g_qf_h  [NH * SEQ * DQK], g_qf_l  [NH * SEQ * DQK];
__device__ bf16 g_k_h   [NKV * SEQ * DQK],g_k_l   [NKV * SEQ * DQK];
__device__ bf16 g_vT_h  [NKV * DV * SEQ], g_vT_l  [NKV * DV * SEQ];
__device__ bf16 g_P_h   [67108864],       g_P_l   [67108864];
__device__ bf16 g_ao_h  [SEQ * NH * DV],  g_ao_l  [SEQ * NH * DV];
// transposed weights [N,K]
__device__ bf16 g_wqaT_h [QRANK * DM],          g_wqaT_l [QRANK * DM];
__device__ bf16 g_wqbT_h [NH * DQK * QRANK],    g_wqbT_l [NH * DQK * QRANK];
__device__ bf16 g_wkvaT_h[KVAN * DM],           g_wkvaT_l[KVAN * DM];
__device__ bf16 g_wkvbT_h[NKV*(DNOPE+DV)*KVRANK], g_wkvbT_l[NKV*(DNOPE+DV)*KVRANK];
__device__ bf16 g_woT_h  [DM * NH * DV],        g_woT_l  [DM * NH * DV];

// ---------------- helpers ----------------
__device__ __forceinline__ uint32_t s2u(const void* p) {
    uint32_t a;
    asm("{ .reg .u64 t; cvta.to.shared.u64 t, %1; cvt.u32.u64 %0, t; }"
        : "=r"(a) : "l"(p));
    return a;
}
__device__ __forceinline__ uint32_t pk(bf16 a, bf16 b) {
    unsigned short ua = *(unsigned short*)&a, ub = *(unsigned short*)&b;
    return (uint32_t)ua | ((uint32_t)ub << 16);
}
__device__ __forceinline__ void bsplit(float x, bf16& h, bf16& l) {
    h = __float2bfloat16_rn(x);
    l = __float2bfloat16_rn(x - __bfloat162float(h));
}
__device__ __forceinline__ void ldm4(uint32_t* r, uint32_t addr) {
    asm volatile("ldmatrix.sync.aligned.m8n8.x4.shared.b16 {%0,%1,%2,%3}, [%4];"
        : "=r"(r[0]), "=r"(r[1]), "=r"(r[2]), "=r"(r[3]) : "r"(addr));
}
__device__ __forceinline__ void mma_bf16(float* c, const uint32_t* a,
                                         uint32_t b0, uint32_t b1) {
    asm volatile("mma.sync.aligned.m16n8k16.row.col.f32.bf16.bf16.f32 "
        "{%0,%1,%2,%3}, {%4,%5,%6,%7}, {%8,%9}, {%0,%1,%2,%3};\n"
        : "+f"(c[0]), "+f"(c[1]), "+f"(c[2]), "+f"(c[3])
        : "r"(a[0]), "r"(a[1]), "r"(a[2]), "r"(a[3]), "r"(b0), "r"(b1));
}
__device__ __forceinline__ void cpa16(uint32_t d, const void* g) {
    asm volatile("cp.async.cg.shared.global [%0], [%1], 16;" :: "r"(d), "l"(g));
}
__device__ __forceinline__ void cpa_commit() {
    asm volatile("cp.async.commit_group;" ::: "memory");
}
template<int n>
__device__ __forceinline__ void cpa_wait() {
    asm volatile("cp.async.wait_group %0;" :: "n"(n) : "memory");
}

// =========== pure-bf16 NT GEMM, 128x128x32, hi/lo 3-pass, cp.async ============
#define SPAD   40
#define TILEB  10240
#define STAGEB 40960
#define OFF_AL 10240
#define OFF_BH 20480
#define OFF_BL 30720
#define DSMEM  (2 * STAGEB)

template<bool KCAP, bool CSKIP, bool NG, bool SPLITC>
__global__ __launch_bounds__(256, 2)
void ntgemm(const bf16* __restrict__ Ah, const bf16* __restrict__ Al,
            const bf16* __restrict__ Bh, const bf16* __restrict__ Bl,
            float* __restrict__ C, bf16* __restrict__ Ch, bf16* __restrict__ Cl,
            int N, int K, int lda, int ldb, int ldc, float scale,
            size_t zA, size_t zB, size_t zC, int zshiftB) {
    extern __shared__ __align__(16) char smem[];

    const int z = blockIdx.z;
    Ah += (size_t)z * zA;  Al += (size_t)z * zA;
    Bh += (size_t)(z >> zshiftB) * zB;  Bl += (size_t)(z >> zshiftB) * zB;

    const int row0 = blockIdx.y * 128;
    const int col0 = blockIdx.x * 128;
    if (CSKIP && col0 > row0 + 127) return;

    int Keff = K;
    if (KCAP) { int lim = row0 + 128; if (lim < Keff) Keff = lim; }
    const int iters = Keff >> 5;

    const int tid = threadIdx.x, lane = tid & 31, wid = tid >> 5;
    const uint32_t sb = s2u(smem);

    const int wm = (wid & 3) * 32;
    const int wn = (wid >> 2) * 64;

    auto issue = [&](int k0, int buf) {
#pragma unroll
        for (int j = 0; j < 8; j++) {
            int i  = (j << 8) | tid;
            int t  = i >> 9;
            int r  = (i >> 2) & 127;
            int qu = i & 3;
            const bf16* gp;
            if (t == 0)      gp = Ah + (size_t)(row0 + r) * lda + k0 + qu * 8;
            else if (t == 1) gp = Al + (size_t)(row0 + r) * lda + k0 + qu * 8;
            else if (t == 2) gp = Bh + (size_t)(col0 + r) * ldb + k0 + qu * 8;
            else             gp = Bl + (size_t)(col0 + r) * ldb + k0 + qu * 8;
            uint32_t d = sb + (uint32_t)buf * STAGEB + (uint32_t)t * TILEB
                         + ((uint32_t)r * SPAD + qu * 8) * 2;
            cpa16(d, gp);
        }
    };

    float acc[2][8][4];
#pragma unroll
    for (int mt = 0; mt < 2; mt++)
#pragma unroll
        for (int nt = 0; nt < 8; nt++)
#pragma unroll
            for (int i = 0; i < 4; i++) acc[mt][nt][i] = 0.f;

    auto compute = [&](int buf) {
        const uint32_t ba = sb + (uint32_t)buf * STAGEB;
#pragma unroll
        for (int s16 = 0; s16 < 32; s16 += 16) {
            uint32_t ah[2][4], al[2][4];
#pragma unroll
            for (int mt = 0; mt < 2; mt++) {
                uint32_t addr = ba + (((uint32_t)(wm + mt * 16 + (lane & 15))) * SPAD
                                      + s16 + ((lane >> 4) << 3)) * 2;
                ldm4(ah[mt], addr);
                ldm4(al[mt], addr + OFF_AL);
            }
#pragma unroll
            for (int p = 0; p < 4; p++) {
                const int g = lane >> 3;
                uint32_t addr = ba + OFF_BH +
                    (((uint32_t)(wn + p * 16 + (lane & 7) + ((g >> 1) << 3))) * SPAD
                     + s16 + ((g & 1) << 3)) * 2;
                uint32_t bh[4], bl[4];
                ldm4(bh, addr);
                ldm4(bl, addr + (OFF_BL - OFF_BH));
#pragma unroll
                for (int mt = 0; mt < 2; mt++) {
                    mma_bf16(acc[mt][2*p],   ah[mt], bh[0], bh[1]);
                    mma_bf16(acc[mt][2*p],   al[mt], bh[0], bh[1]);
                    mma_bf16(acc[mt][2*p],   ah[mt], bl[0], bl[1]);
                    mma_bf16(acc[mt][2*p+1], ah[mt], bh[2], bh[3]);
                    mma_bf16(acc[mt][2*p+1], al[mt], bh[2], bh[3]);
                    mma_bf16(acc[mt][2*p+1], ah[mt], bl[2], bl[3]);
                }
            }
        }
    };

    issue(0, 0);
    cpa_commit();
    if (iters > 1) issue(32, 1);
    cpa_commit();

    for (int it = 0; it < iters; ++it) {
        cpa_wait<1>();
        __syncthreads();
        compute(it & 1);
        __syncthreads();
        if (it + 2 < iters) issue((it + 2) << 5, it & 1);
        cpa_commit();
    }

    const int grp = lane >> 2, tig = lane & 3;
#pragma unroll
    for (int mt = 0; mt < 2; mt++) {
#pragma unroll
        for (int nt = 0; nt < 8; nt++) {
            int r = row0 + wm + mt * 16 + grp;
            int c = col0 + wn + nt * 8 + 2 * tig;
            if (NG && c >= N) continue;
            if (SPLITC) {
                bf16 h0,l0,h1,l1;
                bsplit(acc[mt][nt][0] * scale, h0, l0);
                bsplit(acc[mt][nt][1] * scale, h1, l1);
                size_t o0 = (size_t)r * ldc + c + (size_t)z * zC;
                *(uint32_t*)&Ch[o0] = pk(h0, h1);
                *(uint32_t*)&Cl[o0] = pk(l0, l1);
                bsplit(acc[mt][nt][2] * scale, h0, l0);
                bsplit(acc[mt][nt][3] * scale, h1, l1);
                size_t o1 = (size_t)(r + 8) * ldc + c + (size_t)z * zC;
                *(uint32_t*)&Ch[o1] = pk(h0, h1);
                *(uint32_t*)&Cl[o1] = pk(l0, l1);
            } else {
                float* Cz = C + (size_t)z * zC;
                *(float2*)&Cz[(size_t)r * ldc + c] =
                    make_float2(acc[mt][nt][0] * scale, acc[mt][nt][1] * scale);
                *(float2*)&Cz[(size_t)(r + 8) * ldc + c] =
                    make_float2(acc[mt][nt][2] * scale, acc[mt][nt][3] * scale);
            }
        }
    }
}

// ---------------- elementwise fp32 -> bf16 hi/lo split ----------------
__global__ __launch_bounds__(256)
void split_pair(const float* __restrict__ X, bf16* __restrict__ H,
                bf16* __restrict__ L, int n) {
    int i = (blockIdx.x * 256 + threadIdx.x) * 4;
    if (i >= n) return;
    float4 v = *(const float4*)&X[i];
    bf16 h0,l0,h1,l1,h2,l2,h3,l3;
    bsplit(v.x,h0,l0); bsplit(v.y,h1,l1); bsplit(v.z,h2,l2); bsplit(v.w,h3,l3);
    *(uint2*)&H[i] = make_uint2(pk(h0,h1), pk(h2,h3));
    *(uint2*)&L[i] = make_uint2(pk(l0,l1), pk(l2,l3));
}

// ---------------- weight transpose + split: W[K,N] -> T[Npad,K] bf16 ----------------
__global__ __launch_bounds__(256)
void wsplitT(const float* __restrict__ W, bf16* __restrict__ Th,
             bf16* __restrict__ Tl, int K, int N) {
    __shared__ float t[32][33];
    const int n0 = blockIdx.x * 32, k0 = blockIdx.y * 32;
    const int tx = threadIdx.x & 31, ty = threadIdx.x >> 5;
#pragma unroll
    for (int i = 0; i < 4; i++) {
        int k = k0 + ty + i * 8, n = n0 + tx;
        t[ty + i * 8][tx] = (n < N) ? W[(size_t)k * N + n] : 0.f;
    }
    __syncthreads();
#pragma unroll
    for (int i = 0; i < 4; i++) {
        int n = n0 + ty + i * 8, k = k0 + tx;
        bf16 h, l;
        bsplit(t[tx][ty + i * 8], h, l);
        Th[(size_t)n * K + k] = h;
        Tl[(size_t)n * K + k] = l;
    }
}

// ---------------- rms norm -> bf16 hi/lo ----------------
__global__ __launch_bounds__(256)
void rmsnorm_split(const float* __restrict__ X, bf16* __restrict__ Yh,
                   bf16* __restrict__ Yl, const float* __restrict__ W,
                   int n, int ldx, int ldy) {
    const int r = blockIdx.x;
    const float* x = X + (size_t)r * ldx;
    const int tid = threadIdx.x;
    __shared__ float red[256];

    float ss = 0.f;
    for (int j = tid; j < n; j += 256) { float v = x[j]; ss += v * v; }
    red[tid] = ss; __syncthreads();
    for (int s = 128; s > 0; s >>= 1) {
        if (tid < s) red[tid] += red[tid + s];
        __syncthreads();
    }
    const float rinv = rsqrtf(red[0] / (float)n + 1e-6f);
    for (int j = tid; j < n; j += 256) {
        bf16 h, l;
        bsplit(x[j] * rinv * W[j], h, l);
        Yh[(size_t)r * ldy + j] = h;
        Yl[(size_t)r * ldy + j] = l;
    }
}

// ---------------- causal softmax -> P bf16 hi/lo ----------------
__global__ __launch_bounds__(256)
void softmax_split(const float* __restrict__ Sc, bf16* __restrict__ Ph,
                   bf16* __restrict__ Pl) {
    const int r = blockIdx.x;
    const int q = r & (SEQ - 1);
    const float* row = Sc + (size_t)r * SEQ;
    const int n = q + 1;
    const int kmax = (q & ~127) + 128;
    const int tid = threadIdx.x;
    __shared__ float red[256];

    float m = -INFINITY;
    for (int j = tid; j < n; j += 256) m = fmaxf(m, row[j]);
    red[tid] = m; __syncthreads();
    for (int s = 128; s > 0; s >>= 1) {
        if (tid < s) red[tid] = fmaxf(red[tid], red[tid + s]);
        __syncthreads();
    }
    m = red[0]; __syncthreads();

    float sum = 0.f;
    for (int j = tid; j < n; j += 256) sum += __expf(row[j] - m);
    red[tid] = sum; __syncthreads();
    for (int s = 128; s > 0; s >>= 1) {
        if (tid < s) red[tid] += red[tid + s];
        __syncthreads();
    }
    const float inv = 1.f / red[0];

    bf16* ph = Ph + (size_t)r * SEQ;
    bf16* pl = Pl + (size_t)r * SEQ;
    for (int j = tid; j < n; j += 256) {
        bf16 h, l;
        bsplit(__expf(row[j] - m) * inv, h, l);
        ph[j] = h; pl[j] = l;
    }
    const bf16 zz = __float2bfloat16_rn(0.f);
    for (int j = n + tid; j < kmax; j += 256) { ph[j] = zz; pl[j] = zz; }
}

// ---------------- RoPE + head gather -> bf16 hi/lo (+ V transposed) ----------------
__global__ __launch_bounds__(256)
void rope_gather_split(const float* __restrict__ q,
                       const float* __restrict__ kv,
                       const float* __restrict__ ckv,
                       const float* __restrict__ cosT, const float* __restrict__ sinT,
                       const int* __restrict__ pos,
                       bf16* __restrict__ qfh, bf16* __restrict__ qfl,
                       bf16* __restrict__ kkh, bf16* __restrict__ kkl,
                       bf16* __restrict__ vth, bf16* __restrict__ vtl) {
    const int s = blockIdx.x;
    const int p = pos[s];
    const float* c  = cosT + (size_t)p * DROPE;
    const float* sn = sinT + (size_t)p * DROPE;

    for (int i = threadIdx.x; i < NH * DQK; i += 256) {
        int h = i / DQK, d = i % DQK;
        const float* qr = q + (size_t)s * NH * DQK + h * DQK;
        float val;
        if (d < DNOPE) val = qr[d];
        else {
            int dr = d - DNOPE;
            float x  = qr[d];
            float rh = (dr < DROPE / 2) ? -qr[DNOPE + dr + DROPE / 2]
                                        :  qr[DNOPE + dr - DROPE / 2];
            val = x * c[dr] + rh * sn[dr];
        }
        bf16 hh, ll;
        bsplit(val, hh, ll);
        size_t o = ((size_t)h * SEQ + s) * DQK + d;
        qfh[o] = hh; qfl[o] = ll;
    }
    for (int i = threadIdx.x; i < NKV * DQK; i += 256) {
        int kh2 = i / DQK, d = i % DQK;
        float val;
        if (d < DNOPE) val = kv[(size_t)s * NKV * (DNOPE + DV) + kh2 * (DNOPE + DV) + d];
        else {
            int dr = d - DNOPE;
            const float* kr = ckv + (size_t)s * (KVRANK + DROPE) + KVRANK;
            float x  = kr[dr];
            float rh = (dr < DROPE / 2) ? -kr[dr + DROPE / 2] : kr[dr - DROPE / 2];
            val = x * c[dr] + rh * sn[dr];
        }
        bf16 hh, ll;
        bsplit(val, hh, ll);
        size_t o = ((size_t)kh2 * SEQ + s) * DQK + d;
        kkh[o] = hh; kkl[o] = ll;
    }
    for (int i = threadIdx.x; i < NKV * DV; i += 256) {
        int kh2 = i / DV, d = i % DV;
        float val = kv[(size_t)s * NKV * (DNOPE + DV) + kh2 * (DNOPE + DV) + DNOPE + d];
        bf16 hh, ll;
        bsplit(val, hh, ll);
        size_t o = ((size_t)kh2 * DV + d) * SEQ + s;
        vth[o] = hh; vtl[o] = ll;
    }
}

// ---------------- launch ----------------
extern "C" void kernel_launch(void* const* d_in, const int* in_sizes, int n_in,
                              void* d_out, int out_size) {
    const float* hidden    = (const float*)d_in[0];
    const float* cosT      = (const float*)d_in[1];
    const float* sinT      = (const float*)d_in[2];
    const float* wq_a      = (const float*)d_in[3];
    const float* q_a_ln_w  = (const float*)d_in[4];
    const float* wq_b      = (const float*)d_in[5];
    const float* wkv_a     = (const float*)d_in[6];
    const float* kv_a_ln_w = (const float*)d_in[7];
    const float* wkv_b     = (const float*)d_in[8];
    const float* wo        = (const float*)d_in[9];
    const int*   cpos      = (const int*)d_in[10];
    float* out = (float*)d_out;

    float *qa, *q, *ckv, *kv, *sc;
    bf16 *hidh, *hidl, *qanh, *qanl, *ckvnh, *ckvnl, *qfh, *qfl, *kh, *kl;
    bf16 *vth, *vtl, *Ph, *Pl, *aoh, *aol;
    bf16 *wqaTh, *wqaTl, *wqbTh, *wqbTl, *wkvaTh, *wkvaTl, *wkvbTh, *wkvbTl, *woTh, *woTl;

    cudaGetSymbolAddress((void**)&qa,    g_qa);
    cudaGetSymbolAddress((void**)&q,     g_q);
    cudaGetSymbolAddress((void**)&ckv,   g_ckv);
    cudaGetSymbolAddress((void**)&kv,    g_kv);
    cudaGetSymbolAddress((void**)&sc,    g_sc);
    cudaGetSymbolAddress((void**)&hidh,  g_hid_h);  cudaGetSymbolAddress((void**)&hidl,  g_hid_l);
    cudaGetSymbolAddress((void**)&qanh,  g_qan_h);  cudaGetSymbolAddress((void**)&qanl,  g_qan_l);
    cudaGetSymbolAddress((void**)&ckvnh, g_ckvn_h); cudaGetSymbolAddress((void**)&ckvnl, g_ckvn_l);
    cudaGetSymbolAddress((void**)&qfh,   g_qf_h);   cudaGetSymbolAddress((void**)&qfl,   g_qf_l);
    cudaGetSymbolAddress((void**)&kh,    g_k_h);    cudaGetSymbolAddress((void**)&kl,    g_k_l);
    cudaGetSymbolAddress((void**)&vth,   g_vT_h);   cudaGetSymbolAddress((void**)&vtl,   g_vT_l);
    cudaGetSymbolAddress((void**)&Ph,    g_P_h);    cudaGetSymbolAddress((void**)&Pl,    g_P_l);
    cudaGetSymbolAddress((void**)&aoh,   g_ao_h);   cudaGetSymbolAddress((void**)&aol,   g_ao_l);
    cudaGetSymbolAddress((void**)&wqaTh, g_wqaT_h); cudaGetSymbolAddress((void**)&wqaTl, g_wqaT_l);
    cudaGetSymbolAddress((void**)&wqbTh, g_wqbT_h); cudaGetSymbolAddress((void**)&wqbTl, g_wqbT_l);
    cudaGetSymbolAddress((void**)&wkvaTh,g_wkvaT_h);cudaGetSymbolAddress((void**)&wkvaTl,g_wkvaT_l);
    cudaGetSymbolAddress((void**)&wkvbTh,g_wkvbT_h);cudaGetSymbolAddress((void**)&wkvbTl,g_wkvbT_l);
    cudaGetSymbolAddress((void**)&woTh,  g_woT_h);  cudaGetSymbolAddress((void**)&woTl,  g_woT_l);

    cudaFuncSetAttribute(ntgemm<false,false,false,false>,
        cudaFuncAttributeMaxDynamicSharedMemorySize, DSMEM);
    cudaFuncSetAttribute(ntgemm<false,false,true,false>,
        cudaFuncAttributeMaxDynamicSharedMemorySize, DSMEM);
    cudaFuncSetAttribute(ntgemm<false,true,false,false>,
        cudaFuncAttributeMaxDynamicSharedMemorySize, DSMEM);
    cudaFuncSetAttribute(ntgemm<true,false,false,true>,
        cudaFuncAttributeMaxDynamicSharedMemorySize, DSMEM);

    // 0) operand conversion
    split_pair<<<SEQ*DM/1024, 256>>>(hidden, hidh, hidl, SEQ*DM);
    wsplitT<<<dim3(QRANK/32, DM/32), 256>>>(wq_a,  wqaTh,  wqaTl,  DM,    QRANK);
    wsplitT<<<dim3(NH*DQK/32, QRANK/32), 256>>>(wq_b, wqbTh, wqbTl, QRANK, NH*DQK);
    wsplitT<<<dim3(KVAN/32, DM/32), 256>>>(wkv_a, wkvaTh, wkvaTl, DM,    KVRANK+DROPE);
    wsplitT<<<dim3(NKV*(DNOPE+DV)/32, KVRANK/32), 256>>>(wkv_b, wkvbTh, wkvbTl, KVRANK, NKV*(DNOPE+DV));
    wsplitT<<<dim3(DM/32, NH*DV/32), 256>>>(wo, woTh, woTl, NH*DV, DM);

    // 1) q_a = hidden @ wq_a
    ntgemm<false,false,false,false><<<dim3(QRANK/128, SEQ/128, 1), 256, DSMEM>>>(
        hidh, hidl, wqaTh, wqaTl, qa, 0, 0,
        QRANK, DM, DM, DM, QRANK, 1.f, 0, 0, 0, 0);
    // 2) rmsnorm -> bf16
    rmsnorm_split<<<SEQ, 256>>>(qa, qanh, qanl, q_a_ln_w, QRANK, QRANK, QRANK);
    // 3) q = qan @ wq_b
    ntgemm<false,false,false,false><<<dim3(NH*DQK/128, SEQ/128, 1), 256, DSMEM>>>(
        qanh, qanl, wqbTh, wqbTl, q, 0, 0,
        NH*DQK, QRANK, QRANK, QRANK, NH*DQK, 1.f, 0, 0, 0, 0);
    // 4) ckv = hidden @ wkv_a (N=576, B rows padded to 640)
    ntgemm<false,false,true,false><<<dim3(KVAN/128, SEQ/128, 1), 256, DSMEM>>>(
        hidh, hidl, wkvaTh, wkvaTl, ckv, 0, 0,
        KVRANK+DROPE, DM, DM, DM, KVRANK+DROPE, 1.f, 0, 0, 0, 0);
    // 5) rmsnorm -> bf16
    rmsnorm_split<<<SEQ, 256>>>(ckv, ckvnh, ckvnl, kv_a_ln_w, KVRANK, KVRANK+DROPE, KVRANK);
    // 6) kv = ckvn @ wkv_b
    ntgemm<false,false,false,false><<<dim3(NKV*(DNOPE+DV)/128, SEQ/128, 1), 256, DSMEM>>>(
        ckvnh, ckvnl, wkvbTh, wkvbTl, kv, 0, 0,
        NKV*(DNOPE+DV), KVRANK, KVRANK, KVRANK, NKV*(DNOPE+DV), 1.f, 0, 0, 0, 0);
    // 7) RoPE + gather -> bf16 (V transposed)
    rope_gather_split<<<SEQ, 256>>>(q, kv, ckv, cosT, sinT, cpos,
                                    qfh, qfl, kh, kl, vth, vtl);
    // 8) scores = scale * Qf @ K^T (fp32 out, causal-skipped)
    ntgemm<false,true,false,false><<<dim3(SEQ/128, SEQ/128, NH), 256, DSMEM>>>(
        qfh, qfl, kh, kl, sc, 0, 0,
        SEQ, DQK, DQK, DQK, SEQ, rsqrtf((float)DQK),
        (size_t)SEQ*DQK, (size_t)SEQ*DQK, (size_t)SEQ*SEQ, 2);
    // 9) softmax -> P bf16 hi/lo
    softmax_split<<<NH * SEQ, 256>>>(sc, Ph, Pl);
    // 10) ao = P @ V (K-capped, bf16 split out)
    ntgemm<true,false,false,true><<<dim3(1, SEQ/128, NH), 256, DSMEM>>>(
        Ph, Pl, vth, vtl, 0, aoh, aol,
        DV, SEQ, SEQ, SEQ, NH*DV, 1.f,
        (size_t)SEQ*SEQ, (size_t)DV*SEQ, (size_t)DV, 2);
    // 11) out = ao @ wo
    ntgemm<false,false,false,false><<<dim3(DM/128, SEQ/128, 1), 256, DSMEM>>>(
        aoh, aol, woTh, woTl, out, 0, 0,
        DM, NH*DV, NH*DV, NH*DV, DM, 1.f, 0, 0, 0, 0);
}

// round 12
// speedup vs baseline: 12.5121x; 1.4003x over previous
#include <cuda_runtime.h>
#include <cuda_fp16.h>
#include <math.h>
#include <stdint.h>

#define SEQ   2048
#define NH    16
#define NKV   4
#define DQK   192
#define DNOPE 128
#define DROPE 64
#define DV    128
#define DM    2048
#define QRANK 1536
#define KVRANK 512
#define KVAN  640         // padded N for wkv_a (576 -> 640)

// ---------------- scratch (static device globals; allocation-free) ----------------
__device__ float g_qa  [SEQ * QRANK];
__device__ float g_q   [SEQ * NH * DQK];
__device__ float g_ckv [SEQ * (KVRANK + DROPE)];
__device__ float g_kv  [SEQ * NKV * (DNOPE + DV)];
__device__ float g_sc  [67108864];                    // NH*SEQ*SEQ fp32 scores

__device__ half g_hid_h [SEQ * DM],       g_hid_l [SEQ * DM];
__device__ half g_qan_h [SEQ * QRANK],    g_qan_l [SEQ * QRANK];
__device__ half g_ckvn_h[SEQ * KVRANK],   g_ckvn_l[SEQ * KVRANK];
__device__ half g_qf_h  [NH * SEQ * DQK], g_qf_l  [NH * SEQ * DQK];
__device__ half g_k     [NKV * SEQ * DQK];            // single fp16 (B operand)
__device__ half g_vT    [NKV * DV * SEQ];             // single fp16 (B operand)
__device__ half g_P_h   [67108864],       g_P_l   [67108864];
__device__ half g_ao_h  [SEQ * NH * DV],  g_ao_l  [SEQ * NH * DV];
// transposed weights [N,K], single fp16
__device__ half g_wqaT [QRANK * DM];
__device__ half g_wqbT [NH * DQK * QRANK];
__device__ half g_wkvaT[KVAN * DM];
__device__ half g_wkvbT[NKV*(DNOPE+DV)*KVRANK];
__device__ half g_woT  [DM * NH * DV];

// ---------------- helpers ----------------
__device__ __forceinline__ uint32_t s2u(const void* p) {
    uint32_t a;
    asm("{ .reg .u64 t; cvta.to.shared.u64 t, %1; cvt.u32.u64 %0, t; }"
        : "=r"(a) : "l"(p));
    return a;
}
__device__ __forceinline__ uint32_t pk(half a, half b) {
    unsigned short ua = *(unsigned short*)&a, ub = *(unsigned short*)&b;
    return (uint32_t)ua | ((uint32_t)ub << 16);
}
__device__ __forceinline__ void hsplit(float x, half& h, half& l) {
    h = __float2half_rn(x);
    l = __float2half_rn(x - __half2float(h));
}
__device__ __forceinline__ void ldm4(uint32_t* r, uint32_t addr) {
    asm volatile("ldmatrix.sync.aligned.m8n8.x4.shared.b16 {%0,%1,%2,%3}, [%4];"
        : "=r"(r[0]), "=r"(r[1]), "=r"(r[2]), "=r"(r[3]) : "r"(addr));
}
__device__ __forceinline__ void mma_f16(float* c, const uint32_t* a,
                                        uint32_t b0, uint32_t b1) {
    asm volatile("mma.sync.aligned.m16n8k16.row.col.f32.f16.f16.f32 "
        "{%0,%1,%2,%3}, {%4,%5,%6,%7}, {%8,%9}, {%0,%1,%2,%3};\n"
        : "+f"(c[0]), "+f"(c[1]), "+f"(c[2]), "+f"(c[3])
        : "r"(a[0]), "r"(a[1]), "r"(a[2]), "r"(a[3]), "r"(b0), "r"(b1));
}
__device__ __forceinline__ void cpa16(uint32_t d, const void* g) {
    asm volatile("cp.async.cg.shared.global [%0], [%1], 16;" :: "r"(d), "l"(g));
}
__device__ __forceinline__ void cpa_commit() {
    asm volatile("cp.async.commit_group;" ::: "memory");
}
template<int n>
__device__ __forceinline__ void cpa_wait() {
    asm volatile("cp.async.wait_group %0;" :: "n"(n) : "memory");
}

// ====== fp16 hi/lo 2-pass NT GEMM, 128x128x32, cp.async double buffer =========
// C[M,N] = (Ah+Al)[M,K] @ B[N,K]^T
#define SPAD   40
#define TILEB  10240
#define STAGEB 30720      // 3 tiles: Ah, Al, B
#define OFF_AL 10240
#define OFF_B  20480
#define DSMEM  (2 * STAGEB)

template<bool KCAP, bool CSKIP, bool NG, bool SPLITC>
__global__ __launch_bounds__(256, 2)
void ntgemm(const half* __restrict__ Ah, const half* __restrict__ Al,
            const half* __restrict__ B,
            float* __restrict__ C, half* __restrict__ Ch, half* __restrict__ Cl,
            int N, int K, int lda, int ldb, int ldc, float scale,
            size_t zA, size_t zB, size_t zC, int zshiftB) {
    extern __shared__ __align__(16) char smem[];

    const int z = blockIdx.z;
    Ah += (size_t)z * zA;  Al += (size_t)z * zA;
    B  += (size_t)(z >> zshiftB) * zB;

    const int row0 = blockIdx.y * 128;
    const int col0 = blockIdx.x * 128;
    if (CSKIP && col0 > row0 + 127) return;

    int Keff = K;
    if (KCAP) { int lim = row0 + 128; if (lim < Keff) Keff = lim; }
    const int iters = Keff >> 5;

    const int tid = threadIdx.x, lane = tid & 31, wid = tid >> 5;
    const uint32_t sb = s2u(smem);

    const int wm = (wid & 3) * 32;
    const int wn = (wid >> 2) * 64;

    auto issue = [&](int k0, int buf) {
#pragma unroll
        for (int j = 0; j < 6; j++) {
            int i  = j * 256 + tid;          // 0..1535
            int t  = i >> 9;                 // 0..2
            int r  = (i >> 2) & 127;
            int qu = i & 3;
            const half* gp;
            if (t == 0)      gp = Ah + (size_t)(row0 + r) * lda + k0 + qu * 8;
            else if (t == 1) gp = Al + (size_t)(row0 + r) * lda + k0 + qu * 8;
            else             gp = B  + (size_t)(col0 + r) * ldb + k0 + qu * 8;
            uint32_t d = sb + (uint32_t)buf * STAGEB + (uint32_t)t * TILEB
                         + ((uint32_t)r * SPAD + qu * 8) * 2;
            cpa16(d, gp);
        }
    };

    float acc[2][8][4];
#pragma unroll
    for (int mt = 0; mt < 2; mt++)
#pragma unroll
        for (int nt = 0; nt < 8; nt++)
#pragma unroll
            for (int i = 0; i < 4; i++) acc[mt][nt][i] = 0.f;

    auto compute = [&](int buf) {
        const uint32_t ba = sb + (uint32_t)buf * STAGEB;
#pragma unroll
        for (int s16 = 0; s16 < 32; s16 += 16) {
            uint32_t ah[2][4], al[2][4];
#pragma unroll
            for (int mt = 0; mt < 2; mt++) {
                uint32_t addr = ba + (((uint32_t)(wm + mt * 16 + (lane & 15))) * SPAD
                                      + s16 + ((lane >> 4) << 3)) * 2;
                ldm4(ah[mt], addr);
                ldm4(al[mt], addr + OFF_AL);
            }
#pragma unroll
            for (int p = 0; p < 4; p++) {
                const int g = lane >> 3;
                uint32_t addr = ba + OFF_B +
                    (((uint32_t)(wn + p * 16 + (lane & 7) + ((g >> 1) << 3))) * SPAD
                     + s16 + ((g & 1) << 3)) * 2;
                uint32_t bh[4];
                ldm4(bh, addr);
#pragma unroll
                for (int mt = 0; mt < 2; mt++) {
                    mma_f16(acc[mt][2*p],   ah[mt], bh[0], bh[1]);
                    mma_f16(acc[mt][2*p],   al[mt], bh[0], bh[1]);
                    mma_f16(acc[mt][2*p+1], ah[mt], bh[2], bh[3]);
                    mma_f16(acc[mt][2*p+1], al[mt], bh[2], bh[3]);
                }
            }
        }
    };

    issue(0, 0);
    cpa_commit();
    if (iters > 1) issue(32, 1);
    cpa_commit();

    for (int it = 0; it < iters; ++it) {
        cpa_wait<1>();
        __syncthreads();
        compute(it & 1);
        __syncthreads();
        if (it + 2 < iters) issue((it + 2) << 5, it & 1);
        cpa_commit();
    }

    const int grp = lane >> 2, tig = lane & 3;
#pragma unroll
    for (int mt = 0; mt < 2; mt++) {
#pragma unroll
        for (int nt = 0; nt < 8; nt++) {
            int r = row0 + wm + mt * 16 + grp;
            int c = col0 + wn + nt * 8 + 2 * tig;
            if (NG && c >= N) continue;
            if (SPLITC) {
                half h0,l0,h1,l1;
                hsplit(acc[mt][nt][0] * scale, h0, l0);
                hsplit(acc[mt][nt][1] * scale, h1, l1);
                size_t o0 = (size_t)r * ldc + c + (size_t)z * zC;
                *(uint32_t*)&Ch[o0] = pk(h0, h1);
                *(uint32_t*)&Cl[o0] = pk(l0, l1);
                hsplit(acc[mt][nt][2] * scale, h0, l0);
                hsplit(acc[mt][nt][3] * scale, h1, l1);
                size_t o1 = (size_t)(r + 8) * ldc + c + (size_t)z * zC;
                *(uint32_t*)&Ch[o1] = pk(h0, h1);
                *(uint32_t*)&Cl[o1] = pk(l0, l1);
            } else {
                float* Cz = C + (size_t)z * zC;
                *(float2*)&Cz[(size_t)r * ldc + c] =
                    make_float2(acc[mt][nt][0] * scale, acc[mt][nt][1] * scale);
                *(float2*)&Cz[(size_t)(r + 8) * ldc + c] =
                    make_float2(acc[mt][nt][2] * scale, acc[mt][nt][3] * scale);
            }
        }
    }
}

// ---------------- elementwise fp32 -> fp16 hi/lo split ----------------
__global__ __launch_bounds__(256)
void split_pair(const float* __restrict__ X, half* __restrict__ H,
                half* __restrict__ L, int n) {
    int i = (blockIdx.x * 256 + threadIdx.x) * 4;
    if (i >= n) return;
    float4 v = *(const float4*)&X[i];
    half h0,l0,h1,l1,h2,l2,h3,l3;
    hsplit(v.x,h0,l0); hsplit(v.y,h1,l1); hsplit(v.z,h2,l2); hsplit(v.w,h3,l3);
    *(uint2*)&H[i] = make_uint2(pk(h0,h1), pk(h2,h3));
    *(uint2*)&L[i] = make_uint2(pk(l0,l1), pk(l2,l3));
}

// ---------------- weight transpose (single fp16): W[K,N] -> T[Npad,K] ----------------
__global__ __launch_bounds__(256)
void wsplitT(const float* __restrict__ W, half* __restrict__ T, int K, int N) {
    __shared__ float t[32][33];
    const int n0 = blockIdx.x * 32, k0 = blockIdx.y * 32;
    const int tx = threadIdx.x & 31, ty = threadIdx.x >> 5;
#pragma unroll
    for (int i = 0; i < 4; i++) {
        int k = k0 + ty + i * 8, n = n0 + tx;
        t[ty + i * 8][tx] = (n < N) ? W[(size_t)k * N + n] : 0.f;
    }
    __syncthreads();
#pragma unroll
    for (int i = 0; i < 4; i++) {
        int n = n0 + ty + i * 8, k = k0 + tx;
        T[(size_t)n * K + k] = __float2half_rn(t[tx][ty + i * 8]);
    }
}

// ---------------- rms norm -> fp16 hi/lo ----------------
__global__ __launch_bounds__(256)
void rmsnorm_split(const float* __restrict__ X, half* __restrict__ Yh,
                   half* __restrict__ Yl, const float* __restrict__ W,
                   int n, int ldx, int ldy) {
    const int r = blockIdx.x;
    const float* x = X + (size_t)r * ldx;
    const int tid = threadIdx.x;
    __shared__ float red[256];

    float ss = 0.f;
    for (int j = tid; j < n; j += 256) { float v = x[j]; ss += v * v; }
    red[tid] = ss; __syncthreads();
    for (int s = 128; s > 0; s >>= 1) {
        if (tid < s) red[tid] += red[tid + s];
        __syncthreads();
    }
    const float rinv = rsqrtf(red[0] / (float)n + 1e-6f);
    for (int j = tid; j < n; j += 256) {
        half h, l;
        hsplit(x[j] * rinv * W[j], h, l);
        Yh[(size_t)r * ldy + j] = h;
        Yl[(size_t)r * ldy + j] = l;
    }
}

// ---------------- causal softmax -> P fp16 hi/lo ----------------
__global__ __launch_bounds__(256)
void softmax_split(const float* __restrict__ Sc, half* __restrict__ Ph,
                   half* __restrict__ Pl) {
    const int r = blockIdx.x;
    const int q = r & (SEQ - 1);
    const float* row = Sc + (size_t)r * SEQ;
    const int n = q + 1;
    const int kmax = (q & ~127) + 128;
    const int tid = threadIdx.x;
    __shared__ float red[256];

    float m = -INFINITY;
    for (int j = tid; j < n; j += 256) m = fmaxf(m, row[j]);
    red[tid] = m; __syncthreads();
    for (int s = 128; s > 0; s >>= 1) {
        if (tid < s) red[tid] = fmaxf(red[tid], red[tid + s]);
        __syncthreads();
    }
    m = red[0]; __syncthreads();

    float sum = 0.f;
    for (int j = tid; j < n; j += 256) sum += __expf(row[j] - m);
    red[tid] = sum; __syncthreads();
    for (int s = 128; s > 0; s >>= 1) {
        if (tid < s) red[tid] += red[tid + s];
        __syncthreads();
    }
    const float inv = 1.f / red[0];

    half* ph = Ph + (size_t)r * SEQ;
    half* pl = Pl + (size_t)r * SEQ;
    for (int j = tid; j < n; j += 256) {
        half h, l;
        hsplit(__expf(row[j] - m) * inv, h, l);
        ph[j] = h; pl[j] = l;
    }
    const half zz = __float2half_rn(0.f);
    for (int j = n + tid; j < kmax; j += 256) { ph[j] = zz; pl[j] = zz; }
}

// ---------------- RoPE + head gather -> fp16 (Q split; K,V single) ----------------
__global__ __launch_bounds__(256)
void rope_gather_split(const float* __restrict__ q,
                       const float* __restrict__ kv,
                       const float* __restrict__ ckv,
                       const float* __restrict__ cosT, const float* __restrict__ sinT,
                       const int* __restrict__ pos,
                       half* __restrict__ qfh, half* __restrict__ qfl,
                       half* __restrict__ kk, half* __restrict__ vt) {
    const int s = blockIdx.x;
    const int p = pos[s];
    const float* c  = cosT + (size_t)p * DROPE;
    const float* sn = sinT + (size_t)p * DROPE;

    for (int i = threadIdx.x; i < NH * DQK; i += 256) {
        int h = i / DQK, d = i % DQK;
        const float* qr = q + (size_t)s * NH * DQK + h * DQK;
        float val;
        if (d < DNOPE) val = qr[d];
        else {
            int dr = d - DNOPE;
            float x  = qr[d];
            float rh = (dr < DROPE / 2) ? -qr[DNOPE + dr + DROPE / 2]
                                        :  qr[DNOPE + dr - DROPE / 2];
            val = x * c[dr] + rh * sn[dr];
        }
        half hh, ll;
        hsplit(val, hh, ll);
        size_t o = ((size_t)h * SEQ + s) * DQK + d;
        qfh[o] = hh; qfl[o] = ll;
    }
    for (int i = threadIdx.x; i < NKV * DQK; i += 256) {
        int kh2 = i / DQK, d = i % DQK;
        float val;
        if (d < DNOPE) val = kv[(size_t)s * NKV * (DNOPE + DV) + kh2 * (DNOPE + DV) + d];
        else {
            int dr = d - DNOPE;
            const float* kr = ckv + (size_t)s * (KVRANK + DROPE) + KVRANK;
            float x  = kr[dr];
            float rh = (dr < DROPE / 2) ? -kr[dr + DROPE / 2] : kr[dr - DROPE / 2];
            val = x * c[dr] + rh * sn[dr];
        }
        kk[((size_t)kh2 * SEQ + s) * DQK + d] = __float2half_rn(val);
    }
    for (int i = threadIdx.x; i < NKV * DV; i += 256) {
        int kh2 = i / DV, d = i % DV;
        float val = kv[(size_t)s * NKV * (DNOPE + DV) + kh2 * (DNOPE + DV) + DNOPE + d];
        vt[((size_t)kh2 * DV + d) * SEQ + s] = __float2half_rn(val);
    }
}

// ---------------- launch ----------------
extern "C" void kernel_launch(void* const* d_in, const int* in_sizes, int n_in,
                              void* d_out, int out_size) {
    const float* hidden    = (const float*)d_in[0];
    const float* cosT      = (const float*)d_in[1];
    const float* sinT      = (const float*)d_in[2];
    const float* wq_a      = (const float*)d_in[3];
    const float* q_a_ln_w  = (const float*)d_in[4];
    const float* wq_b      = (const float*)d_in[5];
    const float* wkv_a     = (const float*)d_in[6];
    const float* kv_a_ln_w = (const float*)d_in[7];
    const float* wkv_b     = (const float*)d_in[8];
    const float* wo        = (const float*)d_in[9];
    const int*   cpos      = (const int*)d_in[10];
    float* out = (float*)d_out;

    float *qa, *q, *ckv, *kv, *sc;
    half *hidh, *hidl, *qanh, *qanl, *ckvnh, *ckvnl, *qfh, *qfl, *kk, *vt;
    half *Ph, *Pl, *aoh, *aol;
    half *wqaT, *wqbT, *wkvaT, *wkvbT, *woT;

    cudaGetSymbolAddress((void**)&qa,    g_qa);
    cudaGetSymbolAddress((void**)&q,     g_q);
    cudaGetSymbolAddress((void**)&ckv,   g_ckv);
    cudaGetSymbolAddress((void**)&kv,    g_kv);
    cudaGetSymbolAddress((void**)&sc,    g_sc);
    cudaGetSymbolAddress((void**)&hidh,  g_hid_h);  cudaGetSymbolAddress((void**)&hidl,  g_hid_l);
    cudaGetSymbolAddress((void**)&qanh,  g_qan_h);  cudaGetSymbolAddress((void**)&qanl,  g_qan_l);
    cudaGetSymbolAddress((void**)&ckvnh, g_ckvn_h); cudaGetSymbolAddress((void**)&ckvnl, g_ckvn_l);
    cudaGetSymbolAddress((void**)&qfh,   g_qf_h);   cudaGetSymbolAddress((void**)&qfl,   g_qf_l);
    cudaGetSymbolAddress((void**)&kk,    g_k);
    cudaGetSymbolAddress((void**)&vt,    g_vT);
    cudaGetSymbolAddress((void**)&Ph,    g_P_h);    cudaGetSymbolAddress((void**)&Pl,    g_P_l);
    cudaGetSymbolAddress((void**)&aoh,   g_ao_h);   cudaGetSymbolAddress((void**)&aol,   g_ao_l);
    cudaGetSymbolAddress((void**)&wqaT,  g_wqaT);
    cudaGetSymbolAddress((void**)&wqbT,  g_wqbT);
    cudaGetSymbolAddress((void**)&wkvaT, g_wkvaT);
    cudaGetSymbolAddress((void**)&wkvbT, g_wkvbT);
    cudaGetSymbolAddress((void**)&woT,   g_woT);

    cudaFuncSetAttribute(ntgemm<false,false,false,false>,
        cudaFuncAttributeMaxDynamicSharedMemorySize, DSMEM);
    cudaFuncSetAttribute(ntgemm<false,false,true,false>,
        cudaFuncAttributeMaxDynamicSharedMemorySize, DSMEM);
    cudaFuncSetAttribute(ntgemm<false,true,false,false>,
        cudaFuncAttributeMaxDynamicSharedMemorySize, DSMEM);
    cudaFuncSetAttribute(ntgemm<true,false,false,true>,
        cudaFuncAttributeMaxDynamicSharedMemorySize, DSMEM);

    // 0) operand conversion
    split_pair<<<SEQ*DM/1024, 256>>>(hidden, hidh, hidl, SEQ*DM);
    wsplitT<<<dim3(QRANK/32, DM/32), 256>>>(wq_a,  wqaT,  DM,    QRANK);
    wsplitT<<<dim3(NH*DQK/32, QRANK/32), 256>>>(wq_b, wqbT, QRANK, NH*DQK);
    wsplitT<<<dim3(KVAN/32, DM/32), 256>>>(wkv_a, wkvaT, DM,    KVRANK+DROPE);
    wsplitT<<<dim3(NKV*(DNOPE+DV)/32, KVRANK/32), 256>>>(wkv_b, wkvbT, KVRANK, NKV*(DNOPE+DV));
    wsplitT<<<dim3(DM/32, NH*DV/32), 256>>>(wo, woT, NH*DV, DM);

    // 1) q_a = hidden @ wq_a
    ntgemm<false,false,false,false><<<dim3(QRANK/128, SEQ/128, 1), 256, DSMEM>>>(
        hidh, hidl, wqaT, qa, 0, 0,
        QRANK, DM, DM, DM, QRANK, 1.f, 0, 0, 0, 0);
    // 2) rmsnorm -> fp16 split
    rmsnorm_split<<<SEQ, 256>>>(qa, qanh, qanl, q_a_ln_w, QRANK, QRANK, QRANK);
    // 3) q = qan @ wq_b
    ntgemm<false,false,false,false><<<dim3(NH*DQK/128, SEQ/128, 1), 256, DSMEM>>>(
        qanh, qanl, wqbT, q, 0, 0,
        NH*DQK, QRANK, QRANK, QRANK, NH*DQK, 1.f, 0, 0, 0, 0);
    // 4) ckv = hidden @ wkv_a (N=576, B rows padded to 640)
    ntgemm<false,false,true,false><<<dim3(KVAN/128, SEQ/128, 1), 256, DSMEM>>>(
        hidh, hidl, wkvaT, ckv, 0, 0,
        KVRANK+DROPE, DM, DM, DM, KVRANK+DROPE, 1.f, 0, 0, 0, 0);
    // 5) rmsnorm -> fp16 split
    rmsnorm_split<<<SEQ, 256>>>(ckv, ckvnh, ckvnl, kv_a_ln_w, KVRANK, KVRANK+DROPE, KVRANK);
    // 6) kv = ckvn @ wkv_b
    ntgemm<false,false,false,false><<<dim3(NKV*(DNOPE+DV)/128, SEQ/128, 1), 256, DSMEM>>>(
        ckvnh, ckvnl, wkvbT, kv, 0, 0,
        NKV*(DNOPE+DV), KVRANK, KVRANK, KVRANK, NKV*(DNOPE+DV), 1.f, 0, 0, 0, 0);
    // 7) RoPE + gather -> fp16 (Q split; K,V single; V transposed)
    rope_gather_split<<<SEQ, 256>>>(q, kv, ckv, cosT, sinT, cpos,
                                    qfh, qfl, kk, vt);
    // 8) scores = scale * Qf @ K^T (fp32 out, causal-skipped)
    ntgemm<false,true,false,false><<<dim3(SEQ/128, SEQ/128, NH), 256, DSMEM>>>(
        qfh, qfl, kk, sc, 0, 0,
        SEQ, DQK, DQK, DQK, SEQ, rsqrtf((float)DQK),
        (size_t)SEQ*DQK, (size_t)SEQ*DQK, (size_t)SEQ*SEQ, 2);
    // 9) softmax -> P fp16 hi/lo
    softmax_split<<<NH * SEQ, 256>>>(sc, Ph, Pl);
    // 10) ao = P @ V (K-capped, fp16 split out)
    ntgemm<true,false,false,true><<<dim3(1, SEQ/128, NH), 256, DSMEM>>>(
        Ph, Pl, vt, 0, aoh, aol,
        DV, SEQ, SEQ, SEQ, NH*DV, 1.f,
        (size_t)SEQ*SEQ, (size_t)DV*SEQ, (size_t)DV, 2);
    // 11) out = ao @ wo
    ntgemm<false,false,false,false><<<dim3(DM/128, SEQ/128, 1), 256, DSMEM>>>(
        aoh, aol, woT, out, 0, 0,
        DM, NH*DV, NH*DV, NH*DV, DM, 1.f, 0, 0, 0, 0);
}

// round 13
// speedup vs baseline: 14.6104x; 1.1677x over previous
#include <cuda_runtime.h>
#include <cuda_fp16.h>
#include <math.h>
#include <stdint.h>

#define SEQ   2048
#define NH    16
#define NKV   4
#define DQK   192
#define DNOPE 128
#define DROPE 64
#define DV    128
#define DM    2048
#define QRANK 1536
#define KVRANK 512
#define KVAN  640

// ---------------- scratch (static device globals; allocation-free) ----------------
__device__ float g_qa  [SEQ * QRANK];
__device__ float g_q   [SEQ * NH * DQK];
__device__ float g_ckv [SEQ * (KVRANK + DROPE)];
__device__ float g_kv  [SEQ * NKV * (DNOPE + DV)];

__device__ half g_hid_h [SEQ * DM],       g_hid_l [SEQ * DM];
__device__ half g_qan_h [SEQ * QRANK],    g_qan_l [SEQ * QRANK];
__device__ half g_ckvn_h[SEQ * KVRANK],   g_ckvn_l[SEQ * KVRANK];
__device__ half g_qf_h  [NH * SEQ * DQK], g_qf_l  [NH * SEQ * DQK];
__device__ half g_k     [NKV * SEQ * DQK];
__device__ half g_vT    [NKV * DV * SEQ];
__device__ half g_ao_h  [SEQ * NH * DV],  g_ao_l  [SEQ * NH * DV];
__device__ half g_wqaT [QRANK * DM];
__device__ half g_wqbT [NH * DQK * QRANK];
__device__ half g_wkvaT[KVAN * DM];
__device__ half g_wkvbT[NKV*(DNOPE+DV)*KVRANK];
__device__ half g_woT  [DM * NH * DV];

// ---------------- helpers ----------------
__device__ __forceinline__ uint32_t s2u(const void* p) {
    uint32_t a;
    asm("{ .reg .u64 t; cvta.to.shared.u64 t, %1; cvt.u32.u64 %0, t; }"
        : "=r"(a) : "l"(p));
    return a;
}
__device__ __forceinline__ uint32_t pk(half a, half b) {
    unsigned short ua = *(unsigned short*)&a, ub = *(unsigned short*)&b;
    return (uint32_t)ua | ((uint32_t)ub << 16);
}
__device__ __forceinline__ void hsplit(float x, half& h, half& l) {
    h = __float2half_rn(x);
    l = __float2half_rn(x - __half2float(h));
}
__device__ __forceinline__ void ldm4(uint32_t* r, uint32_t addr) {
    asm volatile("ldmatrix.sync.aligned.m8n8.x4.shared.b16 {%0,%1,%2,%3}, [%4];"
        : "=r"(r[0]), "=r"(r[1]), "=r"(r[2]), "=r"(r[3]) : "r"(addr));
}
__device__ __forceinline__ void mma_f16(float* c, const uint32_t* a,
                                        uint32_t b0, uint32_t b1) {
    asm volatile("mma.sync.aligned.m16n8k16.row.col.f32.f16.f16.f32 "
        "{%0,%1,%2,%3}, {%4,%5,%6,%7}, {%8,%9}, {%0,%1,%2,%3};\n"
        : "+f"(c[0]), "+f"(c[1]), "+f"(c[2]), "+f"(c[3])
        : "r"(a[0]), "r"(a[1]), "r"(a[2]), "r"(a[3]), "r"(b0), "r"(b1));
}
__device__ __forceinline__ void cpa16(uint32_t d, const void* g) {
    asm volatile("cp.async.cg.shared.global [%0], [%1], 16;" :: "r"(d), "l"(g));
}
__device__ __forceinline__ void cpa_commit() {
    asm volatile("cp.async.commit_group;" ::: "memory");
}
template<int n>
__device__ __forceinline__ void cpa_wait() {
    asm volatile("cp.async.wait_group %0;" :: "n"(n) : "memory");
}

// ====== fp16 hi/lo 2-pass NT GEMM, 128x128x32, cp.async double buffer =========
#define SPAD   40
#define TILEB  10240
#define STAGEB 30720
#define OFF_AL 10240
#define OFF_B  20480
#define DSMEM  (2 * STAGEB)

template<bool NG, bool SPLITC>
__global__ __launch_bounds__(256, 2)
void ntgemm(const half* __restrict__ Ah, const half* __restrict__ Al,
            const half* __restrict__ B,
            float* __restrict__ C, half* __restrict__ Ch, half* __restrict__ Cl,
            int N, int K, int lda, int ldb, int ldc) {
    extern __shared__ __align__(16) char smem[];

    const int row0 = blockIdx.y * 128;
    const int col0 = blockIdx.x * 128;
    const int iters = K >> 5;

    const int tid = threadIdx.x, lane = tid & 31, wid = tid >> 5;
    const uint32_t sb = s2u(smem);

    const int wm = (wid & 3) * 32;
    const int wn = (wid >> 2) * 64;

    auto issue = [&](int k0, int buf) {
#pragma unroll
        for (int j = 0; j < 6; j++) {
            int i  = j * 256 + tid;
            int t  = i >> 9;
            int r  = (i >> 2) & 127;
            int qu = i & 3;
            const half* gp;
            if (t == 0)      gp = Ah + (size_t)(row0 + r) * lda + k0 + qu * 8;
            else if (t == 1) gp = Al + (size_t)(row0 + r) * lda + k0 + qu * 8;
            else             gp = B  + (size_t)(col0 + r) * ldb + k0 + qu * 8;
            uint32_t d = sb + (uint32_t)buf * STAGEB + (uint32_t)t * TILEB
                         + ((uint32_t)r * SPAD + qu * 8) * 2;
            cpa16(d, gp);
        }
    };

    float acc[2][8][4];
#pragma unroll
    for (int mt = 0; mt < 2; mt++)
#pragma unroll
        for (int nt = 0; nt < 8; nt++)
#pragma unroll
            for (int i = 0; i < 4; i++) acc[mt][nt][i] = 0.f;

    auto compute = [&](int buf) {
        const uint32_t ba = sb + (uint32_t)buf * STAGEB;
#pragma unroll
        for (int s16 = 0; s16 < 32; s16 += 16) {
            uint32_t ah[2][4], al[2][4];
#pragma unroll
            for (int mt = 0; mt < 2; mt++) {
                uint32_t addr = ba + (((uint32_t)(wm + mt * 16 + (lane & 15))) * SPAD
                                      + s16 + ((lane >> 4) << 3)) * 2;
                ldm4(ah[mt], addr);
                ldm4(al[mt], addr + OFF_AL);
            }
#pragma unroll
            for (int p = 0; p < 4; p++) {
                const int g = lane >> 3;
                uint32_t addr = ba + OFF_B +
                    (((uint32_t)(wn + p * 16 + (lane & 7) + ((g >> 1) << 3))) * SPAD
                     + s16 + ((g & 1) << 3)) * 2;
                uint32_t bh[4];
                ldm4(bh, addr);
#pragma unroll
                for (int mt = 0; mt < 2; mt++) {
                    mma_f16(acc[mt][2*p],   ah[mt], bh[0], bh[1]);
                    mma_f16(acc[mt][2*p],   al[mt], bh[0], bh[1]);
                    mma_f16(acc[mt][2*p+1], ah[mt], bh[2], bh[3]);
                    mma_f16(acc[mt][2*p+1], al[mt], bh[2], bh[3]);
                }
            }
        }
    };

    issue(0, 0);
    cpa_commit();
    if (iters > 1) issue(32, 1);
    cpa_commit();

    for (int it = 0; it < iters; ++it) {
        cpa_wait<1>();
        __syncthreads();
        compute(it & 1);
        __syncthreads();
        if (it + 2 < iters) issue((it + 2) << 5, it & 1);
        cpa_commit();
    }

    const int grp = lane >> 2, tig = lane & 3;
#pragma unroll
    for (int mt = 0; mt < 2; mt++) {
#pragma unroll
        for (int nt = 0; nt < 8; nt++) {
            int r = row0 + wm + mt * 16 + grp;
            int c = col0 + wn + nt * 8 + 2 * tig;
            if (NG && c >= N) continue;
            if (SPLITC) {
                half h0,l0,h1,l1;
                hsplit(acc[mt][nt][0], h0, l0);
                hsplit(acc[mt][nt][1], h1, l1);
                size_t o0 = (size_t)r * ldc + c;
                *(uint32_t*)&Ch[o0] = pk(h0, h1);
                *(uint32_t*)&Cl[o0] = pk(l0, l1);
                hsplit(acc[mt][nt][2], h0, l0);
                hsplit(acc[mt][nt][3], h1, l1);
                size_t o1 = (size_t)(r + 8) * ldc + c;
                *(uint32_t*)&Ch[o1] = pk(h0, h1);
                *(uint32_t*)&Cl[o1] = pk(l0, l1);
            } else {
                *(float2*)&C[(size_t)r * ldc + c] =
                    make_float2(acc[mt][nt][0], acc[mt][nt][1]);
                *(float2*)&C[(size_t)(r + 8) * ldc + c] =
                    make_float2(acc[mt][nt][2], acc[mt][nt][3]);
            }
        }
    }
}

// ================= fused flash attention ======================================
// grid (SEQ/128, NH), 256 threads. Q tile smem-resident (hi/lo), K/V^T streamed.
#define QPAD 200
#define KPAD 200
#define VPAD 72
#define SQH_OFF 0
#define SQL_OFF 51200
#define SK_OFF  102400
#define SK_SZ   25600
#define SV_OFF  153600
#define SV_SZ   18432
#define FA_SMEM 190464

__global__ __launch_bounds__(256, 1)
void flash_attn(const half* __restrict__ Qh, const half* __restrict__ Ql,
                const half* __restrict__ K, const half* __restrict__ VT,
                half* __restrict__ AOh, half* __restrict__ AOl, float scale) {
    extern __shared__ __align__(16) char smem[];
    const int qt = blockIdx.x, h = blockIdx.y;
    const int q0 = qt * 128;
    const int nc = 2 * qt + 2;           // 64-key chunks
    const int kh = h >> 2;

    const int tid = threadIdx.x, lane = tid & 31, wid = tid >> 5;
    const int grp = lane >> 2, tig = lane & 3;
    const uint32_t sb = s2u(smem);

    const half* Qhb = Qh + ((size_t)h * SEQ + q0) * DQK;
    const half* Qlb = Ql + ((size_t)h * SEQ + q0) * DQK;
    const half* Kb  = K  + (size_t)kh * SEQ * DQK;
    const half* Vb  = VT + (size_t)kh * DV * SEQ;

    // ---- issue Q tile (hi+lo): 6144 16B ops / 256 thr = 24 each ----
#pragma unroll
    for (int j = 0; j < 24; j++) {
        int idx = j * 256 + tid;
        int t   = idx / 3072;
        int rem = idx - t * 3072;
        int r   = rem / 24;
        int cc  = (rem % 24) * 8;
        const half* src = (t ? Qlb : Qhb) + (size_t)r * DQK + cc;
        uint32_t dst = sb + (t ? SQL_OFF : SQH_OFF) + ((uint32_t)r * QPAD + cc) * 2;
        cpa16(dst, src);
    }

    auto issue_kv = [&](int c, int buf) {
        const int k0 = c * 64;
#pragma unroll
        for (int j = 0; j < 10; j++) {
            int idx = j * 256 + tid;
            if (idx < 1536) {            // K tile: 64 rows x 24 chunks
                int r = idx / 24, cc = (idx % 24) * 8;
                cpa16(sb + SK_OFF + (uint32_t)buf * SK_SZ + ((uint32_t)r * KPAD + cc) * 2,
                      Kb + (size_t)(k0 + r) * DQK + cc);
            } else {                     // V^T tile: 128 rows x 8 chunks
                int i2 = idx - 1536;
                int d = i2 / 8, cc = (i2 % 8) * 8;
                cpa16(sb + SV_OFF + (uint32_t)buf * SV_SZ + ((uint32_t)d * VPAD + cc) * 2,
                      Vb + (size_t)d * SEQ + k0 + cc);
            }
        }
    };

    // prologue: group0 = Q + chunk0, group1 = chunk1
    issue_kv(0, 0);
    cpa_commit();
    if (nc > 1) issue_kv(1, 1);
    cpa_commit();

    float O[16][4];
#pragma unroll
    for (int dt = 0; dt < 16; dt++)
#pragma unroll
        for (int i = 0; i < 4; i++) O[dt][i] = 0.f;
    float m0 = -1e30f, m1 = -1e30f, l0 = 0.f, l1 = 0.f;

    const int row0 = q0 + wid * 16 + grp;
    const int row1 = row0 + 8;

    for (int c = 0; c < nc; ++c) {
        cpa_wait<1>();
        __syncthreads();
        const int buf = c & 1;
        const uint32_t kbase = sb + SK_OFF + (uint32_t)buf * SK_SZ;
        const uint32_t vbase = sb + SV_OFF + (uint32_t)buf * SV_SZ;
        const int k0 = c * 64;

        // ---- S = Q K^T (2-pass hi/lo) ----
        float S[8][4];
#pragma unroll
        for (int nt = 0; nt < 8; nt++)
#pragma unroll
            for (int i = 0; i < 4; i++) S[nt][i] = 0.f;

#pragma unroll
        for (int s16 = 0; s16 < DQK; s16 += 16) {
            uint32_t ah[4], al[4];
            uint32_t aaddr = sb + (((uint32_t)(wid * 16 + (lane & 15))) * QPAD
                                   + s16 + ((lane >> 4) << 3)) * 2;
            ldm4(ah, aaddr + SQH_OFF);
            ldm4(al, aaddr + SQL_OFF);
#pragma unroll
            for (int p = 0; p < 4; p++) {
                const int g = lane >> 3;
                uint32_t baddr = kbase +
                    (((uint32_t)(p * 16 + (lane & 7) + ((g >> 1) << 3))) * KPAD
                     + s16 + ((g & 1) << 3)) * 2;
                uint32_t bh[4];
                ldm4(bh, baddr);
                mma_f16(S[2*p],   ah, bh[0], bh[1]);
                mma_f16(S[2*p],   al, bh[0], bh[1]);
                mma_f16(S[2*p+1], ah, bh[2], bh[3]);
                mma_f16(S[2*p+1], al, bh[2], bh[3]);
            }
        }

        // ---- scale + causal mask ----
#pragma unroll
        for (int nt = 0; nt < 8; nt++)
#pragma unroll
            for (int i = 0; i < 4; i++) S[nt][i] *= scale;
        if (c >= nc - 2) {
#pragma unroll
            for (int nt = 0; nt < 8; nt++) {
                int col = k0 + (nt >> 1) * 16 + (nt & 1) * 8 + tig * 2;
                if (col     > row0) S[nt][0] = -1e30f;
                if (col + 1 > row0) S[nt][1] = -1e30f;
                if (col     > row1) S[nt][2] = -1e30f;
                if (col + 1 > row1) S[nt][3] = -1e30f;
            }
        }

        // ---- online softmax ----
        float cm0 = -1e30f, cm1 = -1e30f;
#pragma unroll
        for (int nt = 0; nt < 8; nt++) {
            cm0 = fmaxf(cm0, fmaxf(S[nt][0], S[nt][1]));
            cm1 = fmaxf(cm1, fmaxf(S[nt][2], S[nt][3]));
        }
        cm0 = fmaxf(cm0, __shfl_xor_sync(0xffffffff, cm0, 1));
        cm0 = fmaxf(cm0, __shfl_xor_sync(0xffffffff, cm0, 2));
        cm1 = fmaxf(cm1, __shfl_xor_sync(0xffffffff, cm1, 1));
        cm1 = fmaxf(cm1, __shfl_xor_sync(0xffffffff, cm1, 2));
        float mn0 = fmaxf(m0, cm0), mn1 = fmaxf(m1, cm1);
        float a0 = __expf(m0 - mn0), a1 = __expf(m1 - mn1);
        m0 = mn0; m1 = mn1;

        float rs0 = 0.f, rs1 = 0.f;
#pragma unroll
        for (int nt = 0; nt < 8; nt++) {
            S[nt][0] = __expf(S[nt][0] - mn0);
            S[nt][1] = __expf(S[nt][1] - mn0);
            S[nt][2] = __expf(S[nt][2] - mn1);
            S[nt][3] = __expf(S[nt][3] - mn1);
            rs0 += S[nt][0] + S[nt][1];
            rs1 += S[nt][2] + S[nt][3];
        }
        rs0 += __shfl_xor_sync(0xffffffff, rs0, 1);
        rs0 += __shfl_xor_sync(0xffffffff, rs0, 2);
        rs1 += __shfl_xor_sync(0xffffffff, rs1, 1);
        rs1 += __shfl_xor_sync(0xffffffff, rs1, 2);
        l0 = l0 * a0 + rs0;
        l1 = l1 * a1 + rs1;

#pragma unroll
        for (int dt = 0; dt < 16; dt++) {
            O[dt][0] *= a0; O[dt][1] *= a0;
            O[dt][2] *= a1; O[dt][3] *= a1;
        }

        // ---- O += P V  (P split hi/lo in regs) ----
#pragma unroll
        for (int kk = 0; kk < 4; kk++) {
            uint32_t pah[4], pal[4];
            half hh, hl;
            half p0h, p0l, p1h, p1l;
            hsplit(S[2*kk][0], p0h, p0l);  hsplit(S[2*kk][1], p1h, p1l);
            pah[0] = pk(p0h, p1h); pal[0] = pk(p0l, p1l);
            hsplit(S[2*kk][2], p0h, p0l);  hsplit(S[2*kk][3], p1h, p1l);
            pah[1] = pk(p0h, p1h); pal[1] = pk(p0l, p1l);
            hsplit(S[2*kk+1][0], p0h, p0l); hsplit(S[2*kk+1][1], p1h, p1l);
            pah[2] = pk(p0h, p1h); pal[2] = pk(p0l, p1l);
            hsplit(S[2*kk+1][2], p0h, p0l); hsplit(S[2*kk+1][3], p1h, p1l);
            pah[3] = pk(p0h, p1h); pal[3] = pk(p0l, p1l);
            (void)hh; (void)hl;
#pragma unroll
            for (int p2 = 0; p2 < 8; p2++) {
                const int g = lane >> 3;
                uint32_t baddr = vbase +
                    (((uint32_t)(p2 * 16 + (lane & 7) + ((g >> 1) << 3))) * VPAD
                     + kk * 16 + ((g & 1) << 3)) * 2;
                uint32_t bv[4];
                ldm4(bv, baddr);
                mma_f16(O[2*p2],   pah, bv[0], bv[1]);
                mma_f16(O[2*p2],   pal, bv[0], bv[1]);
                mma_f16(O[2*p2+1], pah, bv[2], bv[3]);
                mma_f16(O[2*p2+1], pal, bv[2], bv[3]);
            }
        }

        __syncthreads();
        if (c + 2 < nc) issue_kv(c + 2, buf);
        cpa_commit();
    }

    // ---- epilogue: O/l -> ao hi/lo ----
    const float i0 = 1.f / l0, i1 = 1.f / l1;
#pragma unroll
    for (int dt = 0; dt < 16; dt++) {
        int d = dt * 8 + tig * 2;
        half h0, lo0, h1, lo1;
        hsplit(O[dt][0] * i0, h0, lo0);
        hsplit(O[dt][1] * i0, h1, lo1);
        size_t o0 = (size_t)row0 * (NH * DV) + h * DV + d;
        *(uint32_t*)&AOh[o0] = pk(h0, h1);
        *(uint32_t*)&AOl[o0] = pk(lo0, lo1);
        hsplit(O[dt][2] * i1, h0, lo0);
        hsplit(O[dt][3] * i1, h1, lo1);
        size_t o1 = (size_t)row1 * (NH * DV) + h * DV + d;
        *(uint32_t*)&AOh[o1] = pk(h0, h1);
        *(uint32_t*)&AOl[o1] = pk(lo0, lo1);
    }
}

// ---------------- elementwise fp32 -> fp16 hi/lo split ----------------
__global__ __launch_bounds__(256)
void split_pair(const float* __restrict__ X, half* __restrict__ H,
                half* __restrict__ L, int n) {
    int i = (blockIdx.x * 256 + threadIdx.x) * 4;
    if (i >= n) return;
    float4 v = *(const float4*)&X[i];
    half h0,l0,h1,l1,h2,l2,h3,l3;
    hsplit(v.x,h0,l0); hsplit(v.y,h1,l1); hsplit(v.z,h2,l2); hsplit(v.w,h3,l3);
    *(uint2*)&H[i] = make_uint2(pk(h0,h1), pk(h2,h3));
    *(uint2*)&L[i] = make_uint2(pk(l0,l1), pk(l2,l3));
}

// ---------------- weight transpose: W[K,N] -> T[Npad,K] fp16 ----------------
__global__ __launch_bounds__(256)
void wsplitT(const float* __restrict__ W, half* __restrict__ T, int K, int N) {
    __shared__ float t[32][33];
    const int n0 = blockIdx.x * 32, k0 = blockIdx.y * 32;
    const int tx = threadIdx.x & 31, ty = threadIdx.x >> 5;
#pragma unroll
    for (int i = 0; i < 4; i++) {
        int k = k0 + ty + i * 8, n = n0 + tx;
        t[ty + i * 8][tx] = (n < N) ? W[(size_t)k * N + n] : 0.f;
    }
    __syncthreads();
#pragma unroll
    for (int i = 0; i < 4; i++) {
        int n = n0 + ty + i * 8, k = k0 + tx;
        T[(size_t)n * K + k] = __float2half_rn(t[tx][ty + i * 8]);
    }
}

// ---------------- rms norm -> fp16 hi/lo ----------------
__global__ __launch_bounds__(256)
void rmsnorm_split(const float* __restrict__ X, half* __restrict__ Yh,
                   half* __restrict__ Yl, const float* __restrict__ W,
                   int n, int ldx, int ldy) {
    const int r = blockIdx.x;
    const float* x = X + (size_t)r * ldx;
    const int tid = threadIdx.x;
    __shared__ float red[256];

    float ss = 0.f;
    for (int j = tid; j < n; j += 256) { float v = x[j]; ss += v * v; }
    red[tid] = ss; __syncthreads();
    for (int s = 128; s > 0; s >>= 1) {
        if (tid < s) red[tid] += red[tid + s];
        __syncthreads();
    }
    const float rinv = rsqrtf(red[0] / (float)n + 1e-6f);
    for (int j = tid; j < n; j += 256) {
        half h, l;
        hsplit(x[j] * rinv * W[j], h, l);
        Yh[(size_t)r * ldy + j] = h;
        Yl[(size_t)r * ldy + j] = l;
    }
}

// ---------------- RoPE + head gather -> fp16 (Q split; K,V single) ----------------
__global__ __launch_bounds__(256)
void rope_gather_split(const float* __restrict__ q,
                       const float* __restrict__ kv,
                       const float* __restrict__ ckv,
                       const float* __restrict__ cosT, const float* __restrict__ sinT,
                       const int* __restrict__ pos,
                       half* __restrict__ qfh, half* __restrict__ qfl,
                       half* __restrict__ kk, half* __restrict__ vt) {
    const int s = blockIdx.x;
    const int p = pos[s];
    const float* c  = cosT + (size_t)p * DROPE;
    const float* sn = sinT + (size_t)p * DROPE;

    for (int i = threadIdx.x; i < NH * DQK; i += 256) {
        int h = i / DQK, d = i % DQK;
        const float* qr = q + (size_t)s * NH * DQK + h * DQK;
        float val;
        if (d < DNOPE) val = qr[d];
        else {
            int dr = d - DNOPE;
            float x  = qr[d];
            float rh = (dr < DROPE / 2) ? -qr[DNOPE + dr + DROPE / 2]
                                        :  qr[DNOPE + dr - DROPE / 2];
            val = x * c[dr] + rh * sn[dr];
        }
        half hh, ll;
        hsplit(val, hh, ll);
        size_t o = ((size_t)h * SEQ + s) * DQK + d;
        qfh[o] = hh; qfl[o] = ll;
    }
    for (int i = threadIdx.x; i < NKV * DQK; i += 256) {
        int kh2 = i / DQK, d = i % DQK;
        float val;
        if (d < DNOPE) val = kv[(size_t)s * NKV * (DNOPE + DV) + kh2 * (DNOPE + DV) + d];
        else {
            int dr = d - DNOPE;
            const float* kr = ckv + (size_t)s * (KVRANK + DROPE) + KVRANK;
            float x  = kr[dr];
            float rh = (dr < DROPE / 2) ? -kr[dr + DROPE / 2] : kr[dr - DROPE / 2];
            val = x * c[dr] + rh * sn[dr];
        }
        kk[((size_t)kh2 * SEQ + s) * DQK + d] = __float2half_rn(val);
    }
    for (int i = threadIdx.x; i < NKV * DV; i += 256) {
        int kh2 = i / DV, d = i % DV;
        float val = kv[(size_t)s * NKV * (DNOPE + DV) + kh2 * (DNOPE + DV) + DNOPE + d];
        vt[((size_t)kh2 * DV + d) * SEQ + s] = __float2half_rn(val);
    }
}

// ---------------- launch ----------------
extern "C" void kernel_launch(void* const* d_in, const int* in_sizes, int n_in,
                              void* d_out, int out_size) {
    const float* hidden    = (const float*)d_in[0];
    const float* cosT      = (const float*)d_in[1];
    const float* sinT      = (const float*)d_in[2];
    const float* wq_a      = (const float*)d_in[3];
    const float* q_a_ln_w  = (const float*)d_in[4];
    const float* wq_b      = (const float*)d_in[5];
    const float* wkv_a     = (const float*)d_in[6];
    const float* kv_a_ln_w = (const float*)d_in[7];
    const float* wkv_b     = (const float*)d_in[8];
    const float* wo        = (const float*)d_in[9];
    const int*   cpos      = (const int*)d_in[10];
    float* out = (float*)d_out;

    float *qa, *q, *ckv, *kv;
    half *hidh, *hidl, *qanh, *qanl, *ckvnh, *ckvnl, *qfh, *qfl, *kk, *vt;
    half *aoh, *aol;
    half *wqaT, *wqbT, *wkvaT, *wkvbT, *woT;

    cudaGetSymbolAddress((void**)&qa,    g_qa);
    cudaGetSymbolAddress((void**)&q,     g_q);
    cudaGetSymbolAddress((void**)&ckv,   g_ckv);
    cudaGetSymbolAddress((void**)&kv,    g_kv);
    cudaGetSymbolAddress((void**)&hidh,  g_hid_h);  cudaGetSymbolAddress((void**)&hidl,  g_hid_l);
    cudaGetSymbolAddress((void**)&qanh,  g_qan_h);  cudaGetSymbolAddress((void**)&qanl,  g_qan_l);
    cudaGetSymbolAddress((void**)&ckvnh, g_ckvn_h); cudaGetSymbolAddress((void**)&ckvnl, g_ckvn_l);
    cudaGetSymbolAddress((void**)&qfh,   g_qf_h);   cudaGetSymbolAddress((void**)&qfl,   g_qf_l);
    cudaGetSymbolAddress((void**)&kk,    g_k);
    cudaGetSymbolAddress((void**)&vt,    g_vT);
    cudaGetSymbolAddress((void**)&aoh,   g_ao_h);   cudaGetSymbolAddress((void**)&aol,   g_ao_l);
    cudaGetSymbolAddress((void**)&wqaT,  g_wqaT);
    cudaGetSymbolAddress((void**)&wqbT,  g_wqbT);
    cudaGetSymbolAddress((void**)&wkvaT, g_wkvaT);
    cudaGetSymbolAddress((void**)&wkvbT, g_wkvbT);
    cudaGetSymbolAddress((void**)&woT,   g_woT);

    cudaFuncSetAttribute(ntgemm<false,false>,
        cudaFuncAttributeMaxDynamicSharedMemorySize, DSMEM);
    cudaFuncSetAttribute(ntgemm<true,false>,
        cudaFuncAttributeMaxDynamicSharedMemorySize, DSMEM);
    cudaFuncSetAttribute(flash_attn,
        cudaFuncAttributeMaxDynamicSharedMemorySize, FA_SMEM);

    // 0) operand conversion
    split_pair<<<SEQ*DM/1024, 256>>>(hidden, hidh, hidl, SEQ*DM);
    wsplitT<<<dim3(QRANK/32, DM/32), 256>>>(wq_a,  wqaT,  DM,    QRANK);
    wsplitT<<<dim3(NH*DQK/32, QRANK/32), 256>>>(wq_b, wqbT, QRANK, NH*DQK);
    wsplitT<<<dim3(KVAN/32, DM/32), 256>>>(wkv_a, wkvaT, DM,    KVRANK+DROPE);
    wsplitT<<<dim3(NKV*(DNOPE+DV)/32, KVRANK/32), 256>>>(wkv_b, wkvbT, KVRANK, NKV*(DNOPE+DV));
    wsplitT<<<dim3(DM/32, NH*DV/32), 256>>>(wo, woT, NH*DV, DM);

    // 1) q_a = hidden @ wq_a
    ntgemm<false,false><<<dim3(QRANK/128, SEQ/128), 256, DSMEM>>>(
        hidh, hidl, wqaT, qa, 0, 0, QRANK, DM, DM, DM, QRANK);
    // 2) rmsnorm -> fp16 split
    rmsnorm_split<<<SEQ, 256>>>(qa, qanh, qanl, q_a_ln_w, QRANK, QRANK, QRANK);
    // 3) q = qan @ wq_b
    ntgemm<false,false><<<dim3(NH*DQK/128, SEQ/128), 256, DSMEM>>>(
        qanh, qanl, wqbT, q, 0, 0, NH*DQK, QRANK, QRANK, QRANK, NH*DQK);
    // 4) ckv = hidden @ wkv_a (N=576, B rows padded to 640)
    ntgemm<true,false><<<dim3(KVAN/128, SEQ/128), 256, DSMEM>>>(
        hidh, hidl, wkvaT, ckv, 0, 0, KVRANK+DROPE, DM, DM, DM, KVRANK+DROPE);
    // 5) rmsnorm -> fp16 split
    rmsnorm_split<<<SEQ, 256>>>(ckv, ckvnh, ckvnl, kv_a_ln_w, KVRANK, KVRANK+DROPE, KVRANK);
    // 6) kv = ckvn @ wkv_b
    ntgemm<false,false><<<dim3(NKV*(DNOPE+DV)/128, SEQ/128), 256, DSMEM>>>(
        ckvnh, ckvnl, wkvbT, kv, 0, 0, NKV*(DNOPE+DV), KVRANK, KVRANK, KVRANK, NKV*(DNOPE+DV));
    // 7) RoPE + gather -> fp16 (Q split; K,V single; V transposed)
    rope_gather_split<<<SEQ, 256>>>(q, kv, ckv, cosT, sinT, cpos, qfh, qfl, kk, vt);
    // 8) fused flash attention -> ao hi/lo
    flash_attn<<<dim3(SEQ/128, NH), 256, FA_SMEM>>>(
        qfh, qfl, kk, vt, aoh, aol, rsqrtf((float)DQK));
    // 9) out = ao @ wo
    ntgemm<false,false><<<dim3(DM/128, SEQ/128), 256, DSMEM>>>(
        aoh, aol, woT, out, 0, 0, DM, NH*DV, NH*DV, NH*DV, DM);
}